// round 12
// baseline (speedup 1.0000x reference)
#include <cuda_runtime.h>
#include <math.h>

// Problem constants (fixed-shape problem)
#define NNODES 10000
#define NFACT  20000
#define SSEG   30000      // NNODES + NFACT
#define EEDGE  80000      // 4 * NFACT
#define SD     64         // STATE_DIM == MSG_DIM
#define HM     128        // HID_MSG == HID_RO
#define NSTEPS 10
#define WPAD   264

typedef unsigned long long u64;

// ---------------- persistent device scratch (no allocation allowed) ----------------
__device__ float g_h[SSEG * SD];
__device__ float g_c[SSEG * SD];
__device__ float g_nm[SSEG * SD];
__device__ float g_p[SSEG * 256];               // [P1(128) | P2(128)] per segment
__device__ float g_eaw[EEDGE * HM];             // W1c @ edge_attr + b1, per edge (step-invariant)
__device__ __align__(16) float g_wp[SD * 256 + WPAD];         // [k=64][j=256]
__device__ __align__(16) float g_w1ct[4 * HM];                // [k=4][j=128] = W1c^T
__device__ __align__(16) float g_w2t[HM * HM + WPAD];         // [128][128] = mp_w2^T
__device__ __align__(16) float g_w3t[HM * SD + WPAD];         // [128][64]  = mp_w3^T
__device__ __align__(16) float g_wg[(2 * SD) * (4 * SD) + WPAD]; // [128][256]
__device__ __align__(16) float g_bg[4 * SD];                  // b_ih + b_hh
__device__ __align__(16) float g_ro1t[SD * HM + WPAD];        // [64][128]  = ro_w1^T
__device__ __align__(16) float g_ro2t[HM * HM + WPAD];        // [128][128] = ro_w2^T

__device__ __forceinline__ float sigm(float x) { return 1.f / (1.f + __expf(-x)); }

// ---- Blackwell packed f32x2 helpers (FFMA2: 2 fp32 FMAs per fma-pipe issue) ----
__device__ __forceinline__ u64 pack2(float lo, float hi) {
    u64 r; asm("mov.b64 %0, {%1, %2};" : "=l"(r) : "f"(lo), "f"(hi)); return r;
}
__device__ __forceinline__ void unpack2(u64 v, float& lo, float& hi) {
    asm("mov.b64 {%0, %1}, %2;" : "=f"(lo), "=f"(hi) : "l"(v));
}
__device__ __forceinline__ void fma2(u64& d, u64 a, u64 b) {
    asm("fma.rn.f32x2 %0, %1, %2, %3;" : "=l"(d) : "l"(a), "l"(b), "l"(d));
}

__device__ __forceinline__ void fma8(float* a, float x, const float4 w0, const float4 w1) {
    a[0] = fmaf(x, w0.x, a[0]); a[1] = fmaf(x, w0.y, a[1]);
    a[2] = fmaf(x, w0.z, a[2]); a[3] = fmaf(x, w0.w, a[3]);
    a[4] = fmaf(x, w1.x, a[4]); a[5] = fmaf(x, w1.y, a[5]);
    a[6] = fmaf(x, w1.z, a[6]); a[7] = fmaf(x, w1.w, a[7]);
}

// Register-tiled GEMM using packed f32x2 FMAs.
// Weights are loaded DIRECTLY as packed u64 pairs (bit-identical to float pairs),
// so the only ALU packing left is the per-row scalar broadcast.
// Each thread computes NE interleaved rows (te + i*NT) x 8 cols.
// sIn: shared, row stride SX floats. Wt: global [K][NJ], 16B-aligned rows.
template <int NE, int NT, int K, int NJ, int SX>
__device__ __forceinline__ void tile_gemm(const float* sIn, const float* __restrict__ Wt,
                                          int te, int tj, float acc[][8]) {
    u64 a2[NE][4];
#pragma unroll
    for (int i = 0; i < NE; i++)
#pragma unroll
        for (int p = 0; p < 4; p++) a2[i][p] = 0ull;   // bits(0,0) == (0.f,0.f)
    const float* wbase = Wt + tj * 8;
#pragma unroll 2
    for (int k = 0; k < K; k += 4) {
        float4 xv[NE];
#pragma unroll
        for (int i = 0; i < NE; i++)
            xv[i] = *(const float4*)(sIn + (te + i * NT) * SX + k);
#pragma unroll
        for (int kk = 0; kk < 4; kk++) {
            ulonglong2 wA = *(const ulonglong2*)(wbase + (k + kk) * NJ);
            ulonglong2 wB = *(const ulonglong2*)(wbase + (k + kk) * NJ + 4);
#pragma unroll
            for (int i = 0; i < NE; i++) {
                float x = (&xv[i].x)[kk];
                u64 xx = pack2(x, x);
                fma2(a2[i][0], xx, wA.x);
                fma2(a2[i][1], xx, wA.y);
                fma2(a2[i][2], xx, wB.x);
                fma2(a2[i][3], xx, wB.y);
            }
        }
    }
#pragma unroll
    for (int i = 0; i < NE; i++)
#pragma unroll
        for (int p = 0; p < 4; p++)
            unpack2(a2[i][p], acc[i][2 * p], acc[i][2 * p + 1]);
}

// ---------------- prep: transpose/split weights, combine LSTM biases ----------------
#define PREP_TOTAL (16384 + 512 + 16384 + 8192 + 16384 + 16384 + 256 + 8192 + 16384)
__global__ void k_prep(const float* __restrict__ w1, const float* __restrict__ w2,
                       const float* __restrict__ w3, const float* __restrict__ wih,
                       const float* __restrict__ whh, const float* __restrict__ bih,
                       const float* __restrict__ bhh, const float* __restrict__ r1,
                       const float* __restrict__ r2) {
    int i = blockIdx.x * 256 + threadIdx.x;
    // w1 is [128 out][132 in]; in-dims: 0..63 h[row], 64..127 h[col], 128..131 ea
    if (i < 16384) {
        int j = i & 255, k = i >> 8;   // k<64
        g_wp[k * 256 + j] = (j < 128) ? w1[j * 132 + k] : w1[(j - 128) * 132 + 64 + k];
        return;
    }
    i -= 16384;
    if (i < 512)   { int k = i >> 7, j = i & 127; g_w1ct[k * 128 + j] = w1[j * 132 + 128 + k]; return; }
    i -= 512;
    if (i < 16384) { int j = i / 128, k = i % 128; g_w2t[k * 128 + j] = w2[i]; return; }
    i -= 16384;
    if (i < 8192)  { int j = i / 128, k = i % 128; g_w3t[k * 64 + j] = w3[i]; return; }
    i -= 8192;
    if (i < 16384) { int j = i / 64, k = i % 64; g_wg[k * 256 + j] = wih[i]; return; }
    i -= 16384;
    if (i < 16384) { int j = i / 64, k = i % 64; g_wg[(64 + k) * 256 + j] = whh[i]; return; }
    i -= 16384;
    if (i < 256)   { g_bg[i] = bih[i] + bhh[i]; return; }
    i -= 256;
    if (i < 8192)  { int j = i / 64, k = i % 64; g_ro1t[k * 128 + j] = r1[i]; return; }
    i -= 8192;
    if (i < 16384) { int j = i / 128, k = i % 128; g_ro2t[k * 128 + j] = r2[i]; return; }
}

// eaw[e][j] = b1[j] + sum_{k<4} ea[e][k] * W1c[j][k]   (step-invariant)
__global__ void k_eaw(const float* __restrict__ ea, const float* __restrict__ b1) {
    int gid = blockIdx.x * 256 + threadIdx.x;   // EEDGE*16 threads
    int e = gid >> 4, jg = gid & 15;
    float4 a = *(const float4*)(ea + (size_t)e * 4);
    float o[8];
    float4 bb0 = *(const float4*)(b1 + jg * 8);
    float4 bb1 = *(const float4*)(b1 + jg * 8 + 4);
    o[0] = bb0.x; o[1] = bb0.y; o[2] = bb0.z; o[3] = bb0.w;
    o[4] = bb1.x; o[5] = bb1.y; o[6] = bb1.z; o[7] = bb1.w;
#pragma unroll
    for (int k = 0; k < 4; k++) {
        float av = (&a.x)[k];
        float4 w0 = *(const float4*)(g_w1ct + k * 128 + jg * 8);
        float4 w1 = *(const float4*)(g_w1ct + k * 128 + jg * 8 + 4);
        fma8(o, av, w0, w1);
    }
    float* dst = g_eaw + (size_t)e * 128 + jg * 8;
#pragma unroll
    for (int j = 0; j < 8; j++) dst[j] = o[j];
}

// init h/c/nm and the initial projection P(h0).
__global__ void k_init() {
    int i = blockIdx.x * 256 + threadIdx.x;   // SSEG*256 threads
    if (i < SSEG * SD) {
        g_c[i] = 0.f;
        g_nm[i] = 0.f;
        int s = i >> 6, d = i & 63;
        g_h[i] = (s >= NNODES && d == 0) ? 1.f : 0.f;
    }
    if (i < SSEG * 256) {
        int s = i >> 8, j = i & 255;
        g_p[i] = (s >= NNODES) ? g_wp[j] : 0.f;
    }
}

// ---------------- edge MLP + scatter (64 edges / block, 256 threads) ----------------
// Layer 1: gather-add-relu of precomputed projections (no GEMM).
// NE=4 keeps regs ~70 so 3 blocks/SM (24 warps) fit -> latency hiding.
__global__ __launch_bounds__(256, 3) void k_edge(const int* __restrict__ row,
                                                 const int* __restrict__ col,
                                                 const float* __restrict__ b2,
                                                 const float* __restrict__ b3) {
    __shared__ float sBuf[64 * 132];   // 33.8 KB, aliased across layers
    __shared__ int sRow[64];
    __shared__ int sCol[64];
    const int tid = threadIdx.x;
    const int e0 = blockIdx.x * 64;

    if (tid < 64) sCol[tid] = col[e0 + tid];
    else if (tid < 128) sRow[tid - 64] = row[e0 + tid - 64];
    __syncthreads();

    // layer 1: relu(P1[row] + P2[col] + eaw[e])  -> sBuf
    for (int u = tid; u < 64 * 32; u += 256) {
        int el = u >> 5, part = u & 31;     // part*4 = output j (0..124)
        const float* p1 = g_p + (size_t)sRow[el] * 256 + part * 4;
        const float* p2 = g_p + (size_t)sCol[el] * 256 + 128 + part * 4;
        const float* pe = g_eaw + (size_t)(e0 + el) * 128 + part * 4;
        float4 a = *(const float4*)p1;
        float4 b = *(const float4*)p2;
        float4 z = *(const float4*)pe;
        float4 r;
        r.x = fmaxf(a.x + b.x + z.x, 0.f);
        r.y = fmaxf(a.y + b.y + z.y, 0.f);
        r.z = fmaxf(a.z + b.z + z.z, 0.f);
        r.w = fmaxf(a.w + b.w + z.w, 0.f);
        *(float4*)(sBuf + el * 132 + part * 4) = r;
    }
    __syncthreads();

    // layer 2: 128 -> 128, relu.
    // Accumulate in regs, sync, then overwrite sBuf in place.
    {
        const int te = tid & 15, tj = tid >> 4;   // 16 x (4 edges), 16 x (8 cols)
        float acc[4][8];
        tile_gemm<4, 16, HM, HM, 132>(sBuf, g_w2t, te, tj, acc);
        float4 bb0 = *(const float4*)(b2 + tj * 8);
        float4 bb1 = *(const float4*)(b2 + tj * 8 + 4);
        float bv[8] = {bb0.x, bb0.y, bb0.z, bb0.w, bb1.x, bb1.y, bb1.z, bb1.w};
        __syncthreads();   // all layer-1 reads complete before in-place overwrite
#pragma unroll
        for (int i = 0; i < 4; i++) {
            float* dst = sBuf + (te + i * 16) * 132 + tj * 8;
#pragma unroll
            for (int j = 0; j < 8; j++) dst[j] = fmaxf(acc[i][j] + bv[j], 0.f);
        }
    }
    __syncthreads();

    // layer 3: 128 -> 64, + scatter-add into nm[col]
    {
        const int te = tid & 31, tj = tid >> 5;  // 32 x (2 edges), 8 x (8 outputs)
        float acc[2][8];
        tile_gemm<2, 32, HM, SD, 132>(sBuf, g_w3t, te, tj, acc);
        float4 bb0 = *(const float4*)(b3 + tj * 8);
        float4 bb1 = *(const float4*)(b3 + tj * 8 + 4);
        float bv[8] = {bb0.x, bb0.y, bb0.z, bb0.w, bb1.x, bb1.y, bb1.z, bb1.w};
#pragma unroll
        for (int i = 0; i < 2; i++) {
            float* dst = g_nm + (size_t)sCol[te + i * 32] * SD + tj * 8;
#pragma unroll
            for (int j = 0; j < 8; j++) atomicAdd(dst + j, acc[i][j] + bv[j]);
        }
    }
}

// ------- fused LSTM cell + nm re-zero + next-step projection (32 segs, 256 thr) -------
__global__ __launch_bounds__(256, 3) void k_lstm_proj() {
    __shared__ float sMem[32 * 264];  // sX (32x132) then aliased as sG (32x264)
    __shared__ float sHn[32 * 68];    // h_new staging for the projection GEMM
    float* const sX = sMem;
    float* const sG = sMem;
    const int tid = threadIdx.x;
    const int s0 = blockIdx.x * 32;
    const int te = tid & 7, tj = tid >> 3;

    // load [nm | h] for 32 segments (zero-pad tail)
    for (int u = tid; u < 32 * 32; u += 256) {
        int el = u >> 5, part = u & 31;
        int s = s0 + el;
        float4 v = make_float4(0.f, 0.f, 0.f, 0.f);
        if (s < SSEG) {
            const float* src = (part < 16) ? (g_nm + (size_t)s * SD + part * 4)
                                           : (g_h + (size_t)s * SD + (part - 16) * 4);
            v = *(const float4*)src;
        }
        *(float4*)(sX + el * 132 + part * 4) = v;
    }
    __syncthreads();

    // re-zero the nm rows we just consumed
    for (int u = tid; u < 32 * 16; u += 256) {
        int el = u >> 4, part = u & 15;
        int s = s0 + el;
        if (s < SSEG)
            *(float4*)(g_nm + (size_t)s * SD + part * 4) = make_float4(0.f, 0.f, 0.f, 0.f);
    }

    // gates GEMM: [32 x 128] @ [128 x 256]
    {
        float acc[4][8];
        tile_gemm<4, 8, 2 * SD, 4 * SD, 132>(sX, g_wg, te, tj, acc);
        float4 bb0 = *(const float4*)(g_bg + tj * 8);
        float4 bb1 = *(const float4*)(g_bg + tj * 8 + 4);
        float bv[8] = {bb0.x, bb0.y, bb0.z, bb0.w, bb1.x, bb1.y, bb1.z, bb1.w};
        __syncthreads();  // all sX reads done before aliasing the buffer as sG
#pragma unroll
        for (int i = 0; i < 4; i++)
#pragma unroll
            for (int j = 0; j < 8; j++)
                sG[(te + i * 8) * 264 + tj * 8 + j] = acc[i][j] + bv[j];
    }
    __syncthreads();

    // elementwise LSTM; stage h_new into sHn for the projection
    for (int u = tid; u < 32 * 64; u += 256) {
        int el = u >> 6, d = u & 63;
        int s = s0 + el;
        float hn = 0.f;
        if (s < SSEG) {
            float gi = sG[el * 264 + d];
            float gf = sG[el * 264 + 64 + d];
            float gg = sG[el * 264 + 128 + d];
            float go = sG[el * 264 + 192 + d];
            float c = g_c[(size_t)s * SD + d];
            float cn = sigm(gf) * c + sigm(gi) * tanhf(gg);
            g_c[(size_t)s * SD + d] = cn;
            hn = sigm(go) * tanhf(cn);
            g_h[(size_t)s * SD + d] = hn;
        }
        sHn[el * 68 + d] = hn;
    }
    __syncthreads();

    // projection for next step: P = h_new @ g_wp  ([32 x 64] @ [64 x 256])
    {
        float acc[4][8];
        tile_gemm<4, 8, SD, 256, 68>(sHn, g_wp, te, tj, acc);
#pragma unroll
        for (int i = 0; i < 4; i++) {
            int s = s0 + te + i * 8;
            if (s < SSEG) {
                float* dst = g_p + (size_t)s * 256 + tj * 8;
                *(float4*)dst       = make_float4(acc[i][0], acc[i][1], acc[i][2], acc[i][3]);
                *(float4*)(dst + 4) = make_float4(acc[i][4], acc[i][5], acc[i][6], acc[i][7]);
            }
        }
    }
}

// ---------------- readout MLP + softmax (32 nodes / block, 128 threads) ----------------
__global__ __launch_bounds__(128) void k_readout(const float* __restrict__ b1,
                                                 const float* __restrict__ b2,
                                                 const float* __restrict__ w3,
                                                 const float* __restrict__ b3,
                                                 float* __restrict__ out) {
    __shared__ float sX[32 * 68];
    __shared__ float sA[32 * 132];
    __shared__ float sB[32 * 132];
    const int tid = threadIdx.x;
    const int n0 = blockIdx.x * 32;

    for (int u = tid; u < 32 * 16; u += 128) {
        int el = u >> 4, part = u & 15;
        int n = n0 + el;
        float4 v = make_float4(0.f, 0.f, 0.f, 0.f);
        if (n < NNODES) v = *(const float4*)(g_h + (size_t)n * SD + part * 4);
        *(float4*)(sX + el * 68 + part * 4) = v;
    }
    __syncthreads();
    {
        const int te = tid & 7, tj = tid >> 3;
        float acc[4][8];
        tile_gemm<4, 8, SD, HM, 68>(sX, g_ro1t, te, tj, acc);
        float4 bb0 = *(const float4*)(b1 + tj * 8);
        float4 bb1 = *(const float4*)(b1 + tj * 8 + 4);
        float bv[8] = {bb0.x, bb0.y, bb0.z, bb0.w, bb1.x, bb1.y, bb1.z, bb1.w};
#pragma unroll
        for (int i = 0; i < 4; i++) {
            float* dst = sA + (te + i * 8) * 132 + tj * 8;
#pragma unroll
            for (int j = 0; j < 8; j++) dst[j] = fmaxf(acc[i][j] + bv[j], 0.f);
        }
    }
    __syncthreads();
    {
        const int te = tid & 7, tj = tid >> 3;
        float acc[4][8];
        tile_gemm<4, 8, HM, HM, 132>(sA, g_ro2t, te, tj, acc);
        float4 bb0 = *(const float4*)(b2 + tj * 8);
        float4 bb1 = *(const float4*)(b2 + tj * 8 + 4);
        float bv[8] = {bb0.x, bb0.y, bb0.z, bb0.w, bb1.x, bb1.y, bb1.z, bb1.w};
#pragma unroll
        for (int i = 0; i < 4; i++) {
            float* dst = sB + (te + i * 8) * 132 + tj * 8;
#pragma unroll
            for (int j = 0; j < 8; j++) dst[j] = fmaxf(acc[i][j] + bv[j], 0.f);
        }
    }
    __syncthreads();
    if (tid < 32) {
        int n = n0 + tid;
        if (n < NNODES) {
            float l0 = b3[0], l1 = b3[1];
            const float* x = sB + tid * 132;
#pragma unroll 4
            for (int k = 0; k < HM; k++) {
                l0 = fmaf(x[k], w3[k], l0);
                l1 = fmaf(x[k], w3[HM + k], l1);
            }
            float m = fmaxf(l0, l1);
            float e0 = expf(l0 - m), e1 = expf(l1 - m);
            float inv = 1.f / (e0 + e1);
            out[(size_t)n * 2 + 0] = e0 * inv;
            out[(size_t)n * 2 + 1] = e1 * inv;
        }
    }
}

// ---------------- launch ----------------
extern "C" void kernel_launch(void* const* d_in, const int* in_sizes, int n_in,
                              void* d_out, int out_size) {
    (void)out_size;
    int base = 3;
    if (n_in >= 21 && in_sizes[3] == 1 && in_sizes[4] == 1) base = 5;

    const int* row = (const int*)d_in[0];
    const int* col = (const int*)d_in[1];
    const float* ea = (const float*)d_in[2];
    const float* mp_w1 = (const float*)d_in[base + 0];
    const float* mp_b1 = (const float*)d_in[base + 1];
    const float* mp_w2 = (const float*)d_in[base + 2];
    const float* mp_b2 = (const float*)d_in[base + 3];
    const float* mp_w3 = (const float*)d_in[base + 4];
    const float* mp_b3 = (const float*)d_in[base + 5];
    const float* w_ih  = (const float*)d_in[base + 6];
    const float* w_hh  = (const float*)d_in[base + 7];
    const float* b_ih  = (const float*)d_in[base + 8];
    const float* b_hh  = (const float*)d_in[base + 9];
    const float* ro_w1 = (const float*)d_in[base + 10];
    const float* ro_b1 = (const float*)d_in[base + 11];
    const float* ro_w2 = (const float*)d_in[base + 12];
    const float* ro_b2 = (const float*)d_in[base + 13];
    const float* ro_w3 = (const float*)d_in[base + 14];
    const float* ro_b3 = (const float*)d_in[base + 15];
    float* out = (float*)d_out;

    k_prep<<<(PREP_TOTAL + 255) / 256, 256>>>(mp_w1, mp_w2, mp_w3, w_ih, w_hh,
                                              b_ih, b_hh, ro_w1, ro_w2);
    k_eaw<<<EEDGE * 16 / 256, 256>>>(ea, mp_b1);
    k_init<<<(SSEG * 256 + 255) / 256, 256>>>();

    for (int t = 0; t < NSTEPS; t++) {
        k_edge<<<EEDGE / 64, 256>>>(row, col, mp_b2, mp_b3);
        k_lstm_proj<<<(SSEG + 31) / 32, 256>>>();
    }

    k_readout<<<(NNODES + 31) / 32, 128>>>(ro_b1, ro_b2, ro_w3, ro_b3, out);
}

// round 14
// speedup vs baseline: 1.3396x; 1.3396x over previous
#include <cuda_runtime.h>
#include <cuda_bf16.h>
#include <math.h>
#include <stdint.h>

// Problem constants (fixed-shape problem)
#define NNODES 10000
#define NFACT  20000
#define SSEG   30000      // NNODES + NFACT
#define EEDGE  80000      // 4 * NFACT
#define SD     64         // STATE_DIM == MSG_DIM
#define HM     128        // HID_MSG == HID_RO
#define NSTEPS 10
#define WPAD   264
#define LDX    136        // padded bf16 row stride (272B: conflict-free for ldmatrix)

// ---------------- persistent device scratch (no allocation allowed) ----------------
__device__ float g_h[SSEG * SD];
__device__ float g_c[SSEG * SD];
__device__ float g_nm[SSEG * SD];
__device__ float g_p[SSEG * 256];               // [P1(128) | P2(128)] per segment
__device__ float g_eaw[EEDGE * HM];             // W1c @ edge_attr + b1 (step-invariant)
__device__ __align__(16) float g_wp[SD * 256 + WPAD];         // [k=64][j=256]
__device__ __align__(16) float g_w1ct[4 * HM];                // [k=4][j=128] = W1c^T
__device__ __align__(16) float g_wg[(2 * SD) * (4 * SD) + WPAD]; // [128][256]
__device__ __align__(16) float g_bg[4 * SD];                  // b_ih + b_hh
__device__ __align__(16) float g_ro1t[SD * HM + WPAD];        // [64][128]  = ro_w1^T
__device__ __align__(16) float g_ro2t[HM * HM + WPAD];        // [128][128] = ro_w2^T
// bf16 hi/lo weight image, padded [n][LDX] layout (zero-init covers the pads):
// [W2h(17408) | W2l(17408) | W3h(8704) | W3l(8704)] bf16 elements
#define WIMG_W2H 0
#define WIMG_W2L 17408
#define WIMG_W3H 34816
#define WIMG_W3L 43520
#define WIMG_TOT 52224
__device__ __align__(16) __nv_bfloat16 g_wimg[WIMG_TOT];

__device__ __forceinline__ float sigm(float x) { return 1.f / (1.f + __expf(-x)); }

__device__ __forceinline__ uint32_t smem_to_u32(const void* p) {
    uint32_t a;
    asm("{ .reg .u64 t; cvta.to.shared.u64 t, %1; cvt.u32.u64 %0, t; }" : "=r"(a) : "l"(p));
    return a;
}

// ---- legacy tensor-core primitives (sm_80+; compile for plain sm_100) ----
__device__ __forceinline__ void ldsm_x4(uint32_t& r0, uint32_t& r1, uint32_t& r2, uint32_t& r3,
                                        uint32_t addr) {
    asm volatile("ldmatrix.sync.aligned.m8n8.x4.shared.b16 {%0,%1,%2,%3}, [%4];"
                 : "=r"(r0), "=r"(r1), "=r"(r2), "=r"(r3) : "r"(addr));
}
__device__ __forceinline__ void ldsm_x2(uint32_t& r0, uint32_t& r1, uint32_t addr) {
    asm volatile("ldmatrix.sync.aligned.m8n8.x2.shared.b16 {%0,%1}, [%2];"
                 : "=r"(r0), "=r"(r1) : "r"(addr));
}
__device__ __forceinline__ void mma_bf16(float* c, const uint32_t* a, const uint32_t* b) {
    asm volatile("mma.sync.aligned.m16n8k16.row.col.f32.bf16.bf16.f32 "
                 "{%0,%1,%2,%3}, {%4,%5,%6,%7}, {%8,%9}, {%0,%1,%2,%3};"
                 : "+f"(c[0]), "+f"(c[1]), "+f"(c[2]), "+f"(c[3])
                 : "r"(a[0]), "r"(a[1]), "r"(a[2]), "r"(a[3]), "r"(b[0]), "r"(b[1]));
}

// ---- scalar fp32 GEMM (R9-best) for lstm / projection / readout ----
__device__ __forceinline__ void fma8(float* a, float x, const float4 w0, const float4 w1) {
    a[0] = fmaf(x, w0.x, a[0]); a[1] = fmaf(x, w0.y, a[1]);
    a[2] = fmaf(x, w0.z, a[2]); a[3] = fmaf(x, w0.w, a[3]);
    a[4] = fmaf(x, w1.x, a[4]); a[5] = fmaf(x, w1.y, a[5]);
    a[6] = fmaf(x, w1.z, a[6]); a[7] = fmaf(x, w1.w, a[7]);
}
template <int NE, int NT, int K, int NJ, int SX>
__device__ __forceinline__ void tile_gemm(const float* sIn, const float* __restrict__ Wt,
                                          int te, int tj, float acc[][8]) {
#pragma unroll
    for (int i = 0; i < NE; i++)
#pragma unroll
        for (int j = 0; j < 8; j++) acc[i][j] = 0.f;
    const float* wbase = Wt + tj * 8;
#pragma unroll 2
    for (int k = 0; k < K; k += 4) {
        float4 xv[NE];
#pragma unroll
        for (int i = 0; i < NE; i++)
            xv[i] = *(const float4*)(sIn + (te + i * NT) * SX + k);
#pragma unroll
        for (int kk = 0; kk < 4; kk++) {
            float4 w0 = *(const float4*)(wbase + (k + kk) * NJ);
            float4 w1 = *(const float4*)(wbase + (k + kk) * NJ + 4);
#pragma unroll
            for (int i = 0; i < NE; i++)
                fma8(acc[i], (&xv[i].x)[kk], w0, w1);
        }
    }
}

// ---------------- prep: transpose/split weights, bake bf16 images ----------------
#define PREP_TOTAL (16384 + 512 + 16384 + 8192 + 16384 + 16384 + 256 + 8192 + 16384)
__global__ void k_prep(const float* __restrict__ w1, const float* __restrict__ w2,
                       const float* __restrict__ w3, const float* __restrict__ wih,
                       const float* __restrict__ whh, const float* __restrict__ bih,
                       const float* __restrict__ bhh, const float* __restrict__ r1,
                       const float* __restrict__ r2) {
    int i = blockIdx.x * 256 + threadIdx.x;
    if (i < 16384) {   // g_wp: w1 h-parts split [k=64][j=256]
        int j = i & 255, k = i >> 8;
        g_wp[k * 256 + j] = (j < 128) ? w1[j * 132 + k] : w1[(j - 128) * 132 + 64 + k];
        return;
    }
    i -= 16384;
    if (i < 512)   { int k = i >> 7, j = i & 127; g_w1ct[k * 128 + j] = w1[j * 132 + 128 + k]; return; }
    i -= 512;
    if (i < 16384) {   // W2 bf16 hi/lo, [n][LDX]
        int n = i >> 7, k = i & 127;
        float w = w2[n * 128 + k];
        __nv_bfloat16 h = __float2bfloat16_rn(w);
        __nv_bfloat16 l = __float2bfloat16_rn(w - __bfloat162float(h));
        g_wimg[WIMG_W2H + n * LDX + k] = h;
        g_wimg[WIMG_W2L + n * LDX + k] = l;
        return;
    }
    i -= 16384;
    if (i < 8192)  {   // W3 bf16 hi/lo, [n<64][LDX]
        int n = i >> 7, k = i & 127;
        float w = w3[n * 128 + k];
        __nv_bfloat16 h = __float2bfloat16_rn(w);
        __nv_bfloat16 l = __float2bfloat16_rn(w - __bfloat162float(h));
        g_wimg[WIMG_W3H + n * LDX + k] = h;
        g_wimg[WIMG_W3L + n * LDX + k] = l;
        return;
    }
    i -= 8192;
    if (i < 16384) { int j = i / 64, k = i % 64; g_wg[k * 256 + j] = wih[i]; return; }
    i -= 16384;
    if (i < 16384) { int j = i / 64, k = i % 64; g_wg[(64 + k) * 256 + j] = whh[i]; return; }
    i -= 16384;
    if (i < 256)   { g_bg[i] = bih[i] + bhh[i]; return; }
    i -= 256;
    if (i < 8192)  { int j = i / 64, k = i % 64; g_ro1t[k * 128 + j] = r1[i]; return; }
    i -= 8192;
    if (i < 16384) { int j = i / 128, k = i % 128; g_ro2t[k * 128 + j] = r2[i]; return; }
}

// eaw[e][j] = b1[j] + sum_{k<4} ea[e][k] * W1c[j][k]
__global__ void k_eaw(const float* __restrict__ ea, const float* __restrict__ b1) {
    int gid = blockIdx.x * 256 + threadIdx.x;
    int e = gid >> 4, jg = gid & 15;
    float4 a = *(const float4*)(ea + (size_t)e * 4);
    float o[8];
    float4 bb0 = *(const float4*)(b1 + jg * 8);
    float4 bb1 = *(const float4*)(b1 + jg * 8 + 4);
    o[0] = bb0.x; o[1] = bb0.y; o[2] = bb0.z; o[3] = bb0.w;
    o[4] = bb1.x; o[5] = bb1.y; o[6] = bb1.z; o[7] = bb1.w;
#pragma unroll
    for (int k = 0; k < 4; k++) {
        float av = (&a.x)[k];
        float4 w0 = *(const float4*)(g_w1ct + k * 128 + jg * 8);
        float4 w1 = *(const float4*)(g_w1ct + k * 128 + jg * 8 + 4);
        fma8(o, av, w0, w1);
    }
    float* dst = g_eaw + (size_t)e * 128 + jg * 8;
#pragma unroll
    for (int j = 0; j < 8; j++) dst[j] = o[j];
}

__global__ void k_init() {
    int i = blockIdx.x * 256 + threadIdx.x;
    if (i < SSEG * SD) {
        g_c[i] = 0.f;
        g_nm[i] = 0.f;
        int s = i >> 6, d = i & 63;
        g_h[i] = (s >= NNODES && d == 0) ? 1.f : 0.f;
    }
    if (i < SSEG * 256) {
        int s = i >> 8, j = i & 255;
        g_p[i] = (s >= NNODES) ? g_wp[j] : 0.f;
    }
}

// =============== edge MLP via mma.sync bf16-split (128 edges / CTA, 256 thr) ===============
// smem (dynamic, byte offsets); all 16B-aligned; row stride LDX(=136) bf16 = 272B.
#define SM_XH   0                    // 128*136*2 = 34816
#define SM_XL   34816
#define SM_W2H  69632
#define SM_W2L  104448
#define SM_W3H  139264               // 64*136*2 = 17408
#define SM_W3L  156672
#define SM_B2   174080               // 512B
#define SM_B3   174592               // 256B
#define SM_TOT  174848

__global__ __launch_bounds__(256, 1) void k_edge_mma(const int* __restrict__ row,
                                                     const int* __restrict__ col,
                                                     const float* __restrict__ b2,
                                                     const float* __restrict__ b3) {
    extern __shared__ char smem[];
    const uint32_t sb = smem_to_u32(smem);
    const int tid = threadIdx.x;
    const int wid = tid >> 5, lane = tid & 31;
    const int e0 = blockIdx.x * 128;
    float* b2s = (float*)(smem + SM_B2);
    float* b3s = (float*)(smem + SM_B3);

    if (tid < 128) b2s[tid] = b2[tid];
    else if (tid < 192) b3s[tid - 128] = b3[tid - 128];

    // weights: linear copy of pre-baked image (hi/lo W2 then W3)
    {
        const float4* wsrc = (const float4*)g_wimg;
        float4* wdst = (float4*)(smem + SM_W2H);
        for (int i = tid; i < WIMG_TOT / 8; i += 256) wdst[i] = wsrc[i];
    }
    // gather + layer1 relu + bf16 hi/lo split into padded row-major X
    {
        int el = tid & 127, k0 = (tid >> 7) * 64;
        int r = row[e0 + el], cn = col[e0 + el];
        const float* p1 = g_p + (size_t)r * 256;
        const float* p2 = g_p + (size_t)cn * 256 + 128;
        const float* pe = g_eaw + (size_t)(e0 + el) * 128;
        __nv_bfloat16* xh = (__nv_bfloat16*)(smem + SM_XH) + el * LDX;
        __nv_bfloat16* xl = (__nv_bfloat16*)(smem + SM_XL) + el * LDX;
        for (int k = k0; k < k0 + 64; k += 4) {
            float4 a = *(const float4*)(p1 + k);
            float4 b = *(const float4*)(p2 + k);
            float4 z = *(const float4*)(pe + k);
            float vv[4] = {fmaxf(a.x + b.x + z.x, 0.f), fmaxf(a.y + b.y + z.y, 0.f),
                           fmaxf(a.z + b.z + z.z, 0.f), fmaxf(a.w + b.w + z.w, 0.f)};
#pragma unroll
            for (int q = 0; q < 2; q++) {
                float x0 = vv[2 * q], x1 = vv[2 * q + 1];
                __nv_bfloat16 h0 = __float2bfloat16_rn(x0), h1 = __float2bfloat16_rn(x1);
                __nv_bfloat16 l0 = __float2bfloat16_rn(x0 - __bfloat162float(h0));
                __nv_bfloat16 l1 = __float2bfloat16_rn(x1 - __bfloat162float(h1));
                __nv_bfloat162 hv; hv.x = h0; hv.y = h1;
                __nv_bfloat162 lv; lv.x = l0; lv.y = l1;
                *(__nv_bfloat162*)(xh + k + 2 * q) = hv;
                *(__nv_bfloat162*)(xl + k + 2 * q) = lv;
            }
        }
    }
    __syncthreads();   // ONLY block-wide sync; everything after is warp-local

    const int m0 = wid * 16;                 // this warp's 16 edges
    const int g = lane >> 2, t = lane & 3;   // fragment coords
    // ldmatrix address helpers (byte offsets in shared space)
    const uint32_t aRowOff = (uint32_t)((m0 + (lane & 15)) * LDX + ((lane >> 4) << 3)) * 2;
    const uint32_t bRowSel = (uint32_t)(((lane & 7) * LDX + (((lane >> 3) & 1) << 3)) * 2);

    // ---------------- layer 2: C[16x128] = (Xh+Xl)(W2h+W2l)^T ----------------
    float c[16][4];
#pragma unroll
    for (int j = 0; j < 16; j++)
#pragma unroll
        for (int q = 0; q < 4; q++) c[j][q] = 0.f;

    for (int k0 = 0; k0 < 128; k0 += 16) {
        uint32_t ah[4], al[4];
        ldsm_x4(ah[0], ah[1], ah[2], ah[3], sb + SM_XH + aRowOff + k0 * 2);
        ldsm_x4(al[0], al[1], al[2], al[3], sb + SM_XL + aRowOff + k0 * 2);
#pragma unroll
        for (int j = 0; j < 16; j++) {
            uint32_t bh[2], bl[2];
            uint32_t boff = bRowSel + (uint32_t)(j * 8 * LDX + k0) * 2;
            ldsm_x2(bh[0], bh[1], sb + SM_W2H + boff);
            ldsm_x2(bl[0], bl[1], sb + SM_W2L + boff);
            mma_bf16(c[j], ah, bh);
            mma_bf16(c[j], ah, bl);
            mma_bf16(c[j], al, bh);
        }
    }
    // epilogue: bias+relu, re-split, overwrite own X rows
    {
        __nv_bfloat16* xh = (__nv_bfloat16*)(smem + SM_XH);
        __nv_bfloat16* xl = (__nv_bfloat16*)(smem + SM_XL);
#pragma unroll
        for (int j = 0; j < 16; j++) {
            int col0 = j * 8 + t * 2;
            float bb0 = b2s[col0], bb1 = b2s[col0 + 1];
#pragma unroll
            for (int rr = 0; rr < 2; rr++) {
                int erow = m0 + g + rr * 8;
                float x0 = fmaxf(c[j][2 * rr] + bb0, 0.f);
                float x1 = fmaxf(c[j][2 * rr + 1] + bb1, 0.f);
                __nv_bfloat16 h0 = __float2bfloat16_rn(x0), h1 = __float2bfloat16_rn(x1);
                __nv_bfloat16 l0 = __float2bfloat16_rn(x0 - __bfloat162float(h0));
                __nv_bfloat16 l1 = __float2bfloat16_rn(x1 - __bfloat162float(h1));
                __nv_bfloat162 hv; hv.x = h0; hv.y = h1;
                __nv_bfloat162 lv; lv.x = l0; lv.y = l1;
                *(__nv_bfloat162*)(xh + erow * LDX + col0) = hv;
                *(__nv_bfloat162*)(xl + erow * LDX + col0) = lv;
            }
        }
    }
    __syncwarp();   // epilogue stores visible to this warp's ldmatrix

    // ---------------- layer 3: C2[16x64] = (X2h+X2l)(W3h+W3l)^T ----------------
    float c2[8][4];
#pragma unroll
    for (int j = 0; j < 8; j++)
#pragma unroll
        for (int q = 0; q < 4; q++) c2[j][q] = 0.f;

    for (int k0 = 0; k0 < 128; k0 += 16) {
        uint32_t ah[4], al[4];
        ldsm_x4(ah[0], ah[1], ah[2], ah[3], sb + SM_XH + aRowOff + k0 * 2);
        ldsm_x4(al[0], al[1], al[2], al[3], sb + SM_XL + aRowOff + k0 * 2);
#pragma unroll
        for (int j = 0; j < 8; j++) {
            uint32_t bh[2], bl[2];
            uint32_t boff = bRowSel + (uint32_t)(j * 8 * LDX + k0) * 2;
            ldsm_x2(bh[0], bh[1], sb + SM_W3H + boff);
            ldsm_x2(bl[0], bl[1], sb + SM_W3L + boff);
            mma_bf16(c2[j], ah, bh);
            mma_bf16(c2[j], ah, bl);
            mma_bf16(c2[j], al, bh);
        }
    }
    // epilogue: bias + atomic scatter into nm[col]
    {
        int cA = col[e0 + m0 + g];
        int cB = col[e0 + m0 + g + 8];
        float* dA = g_nm + (size_t)cA * 64;
        float* dB = g_nm + (size_t)cB * 64;
#pragma unroll
        for (int j = 0; j < 8; j++) {
            int col0 = j * 8 + t * 2;
            float bb0 = b3s[col0], bb1 = b3s[col0 + 1];
            atomicAdd(dA + col0,     c2[j][0] + bb0);
            atomicAdd(dA + col0 + 1, c2[j][1] + bb1);
            atomicAdd(dB + col0,     c2[j][2] + bb0);
            atomicAdd(dB + col0 + 1, c2[j][3] + bb1);
        }
    }
}

// ------- fused LSTM cell + nm re-zero + next-step projection (R9-best) -------
__global__ __launch_bounds__(256, 3) void k_lstm_proj() {
    __shared__ float sMem[32 * 264];
    __shared__ float sHn[32 * 68];
    float* const sX = sMem;
    float* const sG = sMem;
    const int tid = threadIdx.x;
    const int s0 = blockIdx.x * 32;
    const int te = tid & 7, tj = tid >> 3;

    for (int u = tid; u < 32 * 32; u += 256) {
        int el = u >> 5, part = u & 31;
        int s = s0 + el;
        float4 v = make_float4(0.f, 0.f, 0.f, 0.f);
        if (s < SSEG) {
            const float* src = (part < 16) ? (g_nm + (size_t)s * SD + part * 4)
                                           : (g_h + (size_t)s * SD + (part - 16) * 4);
            v = *(const float4*)src;
        }
        *(float4*)(sX + el * 132 + part * 4) = v;
    }
    __syncthreads();

    for (int u = tid; u < 32 * 16; u += 256) {
        int el = u >> 4, part = u & 15;
        int s = s0 + el;
        if (s < SSEG)
            *(float4*)(g_nm + (size_t)s * SD + part * 4) = make_float4(0.f, 0.f, 0.f, 0.f);
    }

    {
        float acc[4][8];
        tile_gemm<4, 8, 2 * SD, 4 * SD, 132>(sX, g_wg, te, tj, acc);
        float4 bb0 = *(const float4*)(g_bg + tj * 8);
        float4 bb1 = *(const float4*)(g_bg + tj * 8 + 4);
        float bv[8] = {bb0.x, bb0.y, bb0.z, bb0.w, bb1.x, bb1.y, bb1.z, bb1.w};
        __syncthreads();
#pragma unroll
        for (int i = 0; i < 4; i++)
#pragma unroll
            for (int j = 0; j < 8; j++)
                sG[(te + i * 8) * 264 + tj * 8 + j] = acc[i][j] + bv[j];
    }
    __syncthreads();

    for (int u = tid; u < 32 * 64; u += 256) {
        int el = u >> 6, d = u & 63;
        int s = s0 + el;
        float hn = 0.f;
        if (s < SSEG) {
            float gi = sG[el * 264 + d];
            float gf = sG[el * 264 + 64 + d];
            float gg = sG[el * 264 + 128 + d];
            float go = sG[el * 264 + 192 + d];
            float c = g_c[(size_t)s * SD + d];
            float cn = sigm(gf) * c + sigm(gi) * tanhf(gg);
            g_c[(size_t)s * SD + d] = cn;
            hn = sigm(go) * tanhf(cn);
            g_h[(size_t)s * SD + d] = hn;
        }
        sHn[el * 68 + d] = hn;
    }
    __syncthreads();

    {
        float acc[4][8];
        tile_gemm<4, 8, SD, 256, 68>(sHn, g_wp, te, tj, acc);
#pragma unroll
        for (int i = 0; i < 4; i++) {
            int s = s0 + te + i * 8;
            if (s < SSEG) {
                float* dst = g_p + (size_t)s * 256 + tj * 8;
                *(float4*)dst       = make_float4(acc[i][0], acc[i][1], acc[i][2], acc[i][3]);
                *(float4*)(dst + 4) = make_float4(acc[i][4], acc[i][5], acc[i][6], acc[i][7]);
            }
        }
    }
}

// ---------------- readout MLP + softmax (R9-best) ----------------
__global__ __launch_bounds__(128) void k_readout(const float* __restrict__ b1,
                                                 const float* __restrict__ b2,
                                                 const float* __restrict__ w3,
                                                 const float* __restrict__ b3,
                                                 float* __restrict__ out) {
    __shared__ float sX[32 * 68];
    __shared__ float sA[32 * 132];
    __shared__ float sB[32 * 132];
    const int tid = threadIdx.x;
    const int n0 = blockIdx.x * 32;

    for (int u = tid; u < 32 * 16; u += 128) {
        int el = u >> 4, part = u & 15;
        int n = n0 + el;
        float4 v = make_float4(0.f, 0.f, 0.f, 0.f);
        if (n < NNODES) v = *(const float4*)(g_h + (size_t)n * SD + part * 4);
        *(float4*)(sX + el * 68 + part * 4) = v;
    }
    __syncthreads();
    {
        const int te = tid & 7, tj = tid >> 3;
        float acc[4][8];
        tile_gemm<4, 8, SD, HM, 68>(sX, g_ro1t, te, tj, acc);
        float4 bb0 = *(const float4*)(b1 + tj * 8);
        float4 bb1 = *(const float4*)(b1 + tj * 8 + 4);
        float bv[8] = {bb0.x, bb0.y, bb0.z, bb0.w, bb1.x, bb1.y, bb1.z, bb1.w};
#pragma unroll
        for (int i = 0; i < 4; i++) {
            float* dst = sA + (te + i * 8) * 132 + tj * 8;
#pragma unroll
            for (int j = 0; j < 8; j++) dst[j] = fmaxf(acc[i][j] + bv[j], 0.f);
        }
    }
    __syncthreads();
    {
        const int te = tid & 7, tj = tid >> 3;
        float acc[4][8];
        tile_gemm<4, 8, HM, HM, 132>(sA, g_ro2t, te, tj, acc);
        float4 bb0 = *(const float4*)(b2 + tj * 8);
        float4 bb1 = *(const float4*)(b2 + tj * 8 + 4);
        float bv[8] = {bb0.x, bb0.y, bb0.z, bb0.w, bb1.x, bb1.y, bb1.z, bb1.w};
#pragma unroll
        for (int i = 0; i < 4; i++) {
            float* dst = sB + (te + i * 8) * 132 + tj * 8;
#pragma unroll
            for (int j = 0; j < 8; j++) dst[j] = fmaxf(acc[i][j] + bv[j], 0.f);
        }
    }
    __syncthreads();
    if (tid < 32) {
        int n = n0 + tid;
        if (n < NNODES) {
            float l0 = b3[0], l1 = b3[1];
            const float* x = sB + tid * 132;
#pragma unroll 4
            for (int k = 0; k < HM; k++) {
                l0 = fmaf(x[k], w3[k], l0);
                l1 = fmaf(x[k], w3[HM + k], l1);
            }
            float m = fmaxf(l0, l1);
            float e0 = expf(l0 - m), e1 = expf(l1 - m);
            float inv = 1.f / (e0 + e1);
            out[(size_t)n * 2 + 0] = e0 * inv;
            out[(size_t)n * 2 + 1] = e1 * inv;
        }
    }
}

// ---------------- launch ----------------
extern "C" void kernel_launch(void* const* d_in, const int* in_sizes, int n_in,
                              void* d_out, int out_size) {
    (void)out_size;
    int base = 3;
    if (n_in >= 21 && in_sizes[3] == 1 && in_sizes[4] == 1) base = 5;

    const int* row = (const int*)d_in[0];
    const int* col = (const int*)d_in[1];
    const float* ea = (const float*)d_in[2];
    const float* mp_w1 = (const float*)d_in[base + 0];
    const float* mp_b1 = (const float*)d_in[base + 1];
    const float* mp_w2 = (const float*)d_in[base + 2];
    const float* mp_b2 = (const float*)d_in[base + 3];
    const float* mp_w3 = (const float*)d_in[base + 4];
    const float* mp_b3 = (const float*)d_in[base + 5];
    const float* w_ih  = (const float*)d_in[base + 6];
    const float* w_hh  = (const float*)d_in[base + 7];
    const float* b_ih  = (const float*)d_in[base + 8];
    const float* b_hh  = (const float*)d_in[base + 9];
    const float* ro_w1 = (const float*)d_in[base + 10];
    const float* ro_b1 = (const float*)d_in[base + 11];
    const float* ro_w2 = (const float*)d_in[base + 12];
    const float* ro_b2 = (const float*)d_in[base + 13];
    const float* ro_w3 = (const float*)d_in[base + 14];
    const float* ro_b3 = (const float*)d_in[base + 15];
    float* out = (float*)d_out;

    cudaFuncSetAttribute(k_edge_mma, cudaFuncAttributeMaxDynamicSharedMemorySize, SM_TOT);

    k_prep<<<(PREP_TOTAL + 255) / 256, 256>>>(mp_w1, mp_w2, mp_w3, w_ih, w_hh,
                                              b_ih, b_hh, ro_w1, ro_w2);
    k_eaw<<<EEDGE * 16 / 256, 256>>>(ea, mp_b1);
    k_init<<<(SSEG * 256 + 255) / 256, 256>>>();

    for (int t = 0; t < NSTEPS; t++) {
        k_edge_mma<<<EEDGE / 128, 256, SM_TOT>>>(row, col, mp_b2, mp_b3);
        k_lstm_proj<<<(SSEG + 31) / 32, 256>>>();
    }

    k_readout<<<(NNODES + 31) / 32, 128>>>(ro_b1, ro_b2, ro_w3, ro_b3, out);
}

// round 16
// speedup vs baseline: 1.5281x; 1.1407x over previous
#include <cuda_runtime.h>
#include <cuda_bf16.h>
#include <math.h>
#include <stdint.h>

// Problem constants (fixed-shape problem)
#define NNODES 10000
#define NFACT  20000
#define SSEG   30000      // NNODES + NFACT
#define EEDGE  80000      // 4 * NFACT
#define SD     64         // STATE_DIM == MSG_DIM
#define HM     128        // HID_MSG == HID_RO
#define NSTEPS 10
#define WPAD   264
#define LDX    136        // padded bf16 row stride (272B = 16*17: ldmatrix-aligned, conflict-free)
#define LDKP   72         // proj-weight padded k-stride (144B = 16*9: ldmatrix-aligned)

// ---------------- persistent device scratch (no allocation allowed) ----------------
__device__ float g_h[SSEG * SD];
__device__ float g_c[SSEG * SD];
__device__ float g_nm[SSEG * SD];
__device__ float g_p[SSEG * 256];               // [P1(128) | P2(128)] per segment
__device__ float g_eaw[EEDGE * HM];             // W1c @ edge_attr + b1 (step-invariant)
__device__ __align__(16) float g_wp[SD * 256 + WPAD];         // [k=64][j=256]
__device__ __align__(16) float g_w1ct[4 * HM];                // [k=4][j=128] = W1c^T
__device__ __align__(16) float g_bg[4 * SD];                  // b_ih + b_hh
__device__ __align__(16) float g_ro1t[SD * HM + WPAD];        // [64][128]  = ro_w1^T
__device__ __align__(16) float g_ro2t[HM * HM + WPAD];        // [128][128] = ro_w2^T
// bf16 hi/lo edge-weight image, padded [n][LDX]:
// [W2h(17408) | W2l(17408) | W3h(8704) | W3l(8704)] bf16 elements
#define WIMG_W2H 0
#define WIMG_W2L 17408
#define WIMG_W3H 34816
#define WIMG_W3L 43520
#define WIMG_TOT 52224
__device__ __align__(16) __nv_bfloat16 g_wimg[WIMG_TOT];
// LSTM gates weight image [n=256][k=LDX pad]: hi at 0, lo at 256*LDX
__device__ __align__(16) __nv_bfloat16 g_wgimg[2 * 256 * LDX];
// projection weight image [n=256][k=LDKP pad]: hi at 0, lo at 256*LDKP
__device__ __align__(16) __nv_bfloat16 g_wpimg[2 * 256 * LDKP];

__device__ __forceinline__ float sigm(float x) { return 1.f / (1.f + __expf(-x)); }

__device__ __forceinline__ uint32_t smem_to_u32(const void* p) {
    uint32_t a;
    asm("{ .reg .u64 t; cvta.to.shared.u64 t, %1; cvt.u32.u64 %0, t; }" : "=r"(a) : "l"(p));
    return a;
}

// ---- legacy tensor-core primitives (sm_80+; compile for plain sm_100) ----
__device__ __forceinline__ void ldsm_x4(uint32_t& r0, uint32_t& r1, uint32_t& r2, uint32_t& r3,
                                        uint32_t addr) {
    asm volatile("ldmatrix.sync.aligned.m8n8.x4.shared.b16 {%0,%1,%2,%3}, [%4];"
                 : "=r"(r0), "=r"(r1), "=r"(r2), "=r"(r3) : "r"(addr));
}
__device__ __forceinline__ void ldsm_x2(uint32_t& r0, uint32_t& r1, uint32_t addr) {
    asm volatile("ldmatrix.sync.aligned.m8n8.x2.shared.b16 {%0,%1}, [%2];"
                 : "=r"(r0), "=r"(r1) : "r"(addr));
}
__device__ __forceinline__ void mma_bf16(float* c, const uint32_t* a, const uint32_t* b) {
    asm volatile("mma.sync.aligned.m16n8k16.row.col.f32.bf16.bf16.f32 "
                 "{%0,%1,%2,%3}, {%4,%5,%6,%7}, {%8,%9}, {%0,%1,%2,%3};"
                 : "+f"(c[0]), "+f"(c[1]), "+f"(c[2]), "+f"(c[3])
                 : "r"(a[0]), "r"(a[1]), "r"(a[2]), "r"(a[3]), "r"(b[0]), "r"(b[1]));
}
// split a float pair into bf16 hi/lo packed halves
__device__ __forceinline__ void split2(float x0, float x1, __nv_bfloat162& hv, __nv_bfloat162& lv) {
    __nv_bfloat16 h0 = __float2bfloat16_rn(x0), h1 = __float2bfloat16_rn(x1);
    hv.x = h0; hv.y = h1;
    lv.x = __float2bfloat16_rn(x0 - __bfloat162float(h0));
    lv.y = __float2bfloat16_rn(x1 - __bfloat162float(h1));
}

// ---- scalar fp32 GEMM (for readout) ----
__device__ __forceinline__ void fma8(float* a, float x, const float4 w0, const float4 w1) {
    a[0] = fmaf(x, w0.x, a[0]); a[1] = fmaf(x, w0.y, a[1]);
    a[2] = fmaf(x, w0.z, a[2]); a[3] = fmaf(x, w0.w, a[3]);
    a[4] = fmaf(x, w1.x, a[4]); a[5] = fmaf(x, w1.y, a[5]);
    a[6] = fmaf(x, w1.z, a[6]); a[7] = fmaf(x, w1.w, a[7]);
}
template <int NE, int NT, int K, int NJ, int SX>
__device__ __forceinline__ void tile_gemm(const float* sIn, const float* __restrict__ Wt,
                                          int te, int tj, float acc[][8]) {
#pragma unroll
    for (int i = 0; i < NE; i++)
#pragma unroll
        for (int j = 0; j < 8; j++) acc[i][j] = 0.f;
    const float* wbase = Wt + tj * 8;
#pragma unroll 2
    for (int k = 0; k < K; k += 4) {
        float4 xv[NE];
#pragma unroll
        for (int i = 0; i < NE; i++)
            xv[i] = *(const float4*)(sIn + (te + i * NT) * SX + k);
#pragma unroll
        for (int kk = 0; kk < 4; kk++) {
            float4 w0 = *(const float4*)(wbase + (k + kk) * NJ);
            float4 w1 = *(const float4*)(wbase + (k + kk) * NJ + 4);
#pragma unroll
            for (int i = 0; i < NE; i++)
                fma8(acc[i], (&xv[i].x)[kk], w0, w1);
        }
    }
}

// ---------------- prep: transpose/split weights, bake bf16 images ----------------
#define PREP_TOTAL (16384 + 512 + 16384 + 8192 + 32768 + 16384 + 256 + 8192 + 16384)
__global__ void k_prep(const float* __restrict__ w1, const float* __restrict__ w2,
                       const float* __restrict__ w3, const float* __restrict__ wih,
                       const float* __restrict__ whh, const float* __restrict__ bih,
                       const float* __restrict__ bhh, const float* __restrict__ r1,
                       const float* __restrict__ r2) {
    int i = blockIdx.x * 256 + threadIdx.x;
    if (i < 16384) {   // g_wp: w1 h-parts split [k=64][j=256]
        int j = i & 255, k = i >> 8;
        g_wp[k * 256 + j] = (j < 128) ? w1[j * 132 + k] : w1[(j - 128) * 132 + 64 + k];
        return;
    }
    i -= 16384;
    if (i < 512)   { int k = i >> 7, j = i & 127; g_w1ct[k * 128 + j] = w1[j * 132 + 128 + k]; return; }
    i -= 512;
    if (i < 16384) {   // W2 bf16 hi/lo, [n][LDX]
        int n = i >> 7, k = i & 127;
        float w = w2[n * 128 + k];
        __nv_bfloat16 h = __float2bfloat16_rn(w);
        g_wimg[WIMG_W2H + n * LDX + k] = h;
        g_wimg[WIMG_W2L + n * LDX + k] = __float2bfloat16_rn(w - __bfloat162float(h));
        return;
    }
    i -= 16384;
    if (i < 8192)  {   // W3 bf16 hi/lo, [n<64][LDX]
        int n = i >> 7, k = i & 127;
        float w = w3[n * 128 + k];
        __nv_bfloat16 h = __float2bfloat16_rn(w);
        g_wimg[WIMG_W3H + n * LDX + k] = h;
        g_wimg[WIMG_W3L + n * LDX + k] = __float2bfloat16_rn(w - __bfloat162float(h));
        return;
    }
    i -= 8192;
    if (i < 32768) {   // LSTM gates image [n=256][k=128]: k<64 -> w_ih, else w_hh
        int n = i >> 7, k = i & 127;
        float w = (k < 64) ? wih[n * 64 + k] : whh[n * 64 + (k - 64)];
        __nv_bfloat16 h = __float2bfloat16_rn(w);
        g_wgimg[n * LDX + k] = h;
        g_wgimg[256 * LDX + n * LDX + k] = __float2bfloat16_rn(w - __bfloat162float(h));
        return;
    }
    i -= 32768;
    if (i < 16384) {   // proj image [n=256][k=64] = w1 h-parts (B operand)
        int n = i >> 6, k = i & 63;
        float w = (n < 128) ? w1[n * 132 + k] : w1[(n - 128) * 132 + 64 + k];
        __nv_bfloat16 h = __float2bfloat16_rn(w);
        g_wpimg[n * LDKP + k] = h;
        g_wpimg[256 * LDKP + n * LDKP + k] = __float2bfloat16_rn(w - __bfloat162float(h));
        return;
    }
    i -= 16384;
    if (i < 256)   { g_bg[i] = bih[i] + bhh[i]; return; }
    i -= 256;
    if (i < 8192)  { int j = i / 64, k = i % 64; g_ro1t[k * 128 + j] = r1[i]; return; }
    i -= 8192;
    if (i < 16384) { int j = i / 128, k = i % 128; g_ro2t[k * 128 + j] = r2[i]; return; }
}

// zero the k-pad columns of the bf16 images (k=128..LDX / 64..LDKP) so mma reads 0s
__global__ void k_prep_pads() {
    int i = blockIdx.x * 256 + threadIdx.x;
    // g_wimg pads: [n][128..135] for 4 sections of 128/64 rows
    if (i < 128 * 8) { int n = i >> 3, k = 128 + (i & 7); g_wimg[WIMG_W2H + n * LDX + k] = __nv_bfloat16(0.f); return; }
    i -= 1024;
    if (i < 128 * 8) { int n = i >> 3, k = 128 + (i & 7); g_wimg[WIMG_W2L + n * LDX + k] = __nv_bfloat16(0.f); return; }
    i -= 1024;
    if (i < 64 * 8)  { int n = i >> 3, k = 128 + (i & 7); g_wimg[WIMG_W3H + n * LDX + k] = __nv_bfloat16(0.f); return; }
    i -= 512;
    if (i < 64 * 8)  { int n = i >> 3, k = 128 + (i & 7); g_wimg[WIMG_W3L + n * LDX + k] = __nv_bfloat16(0.f); return; }
    i -= 512;
    if (i < 256 * 8) { int n = i >> 3, k = 128 + (i & 7); g_wgimg[n * LDX + k] = __nv_bfloat16(0.f); return; }
    i -= 2048;
    if (i < 256 * 8) { int n = i >> 3, k = 128 + (i & 7); g_wgimg[256 * LDX + n * LDX + k] = __nv_bfloat16(0.f); return; }
    i -= 2048;
    if (i < 256 * 8) { int n = i >> 3, k = 64 + (i & 7); g_wpimg[n * LDKP + k] = __nv_bfloat16(0.f); return; }
    i -= 2048;
    if (i < 256 * 8) { int n = i >> 3, k = 64 + (i & 7); g_wpimg[256 * LDKP + n * LDKP + k] = __nv_bfloat16(0.f); return; }
}

// eaw[e][j] = b1[j] + sum_{k<4} ea[e][k] * W1c[j][k]
__global__ void k_eaw(const float* __restrict__ ea, const float* __restrict__ b1) {
    int gid = blockIdx.x * 256 + threadIdx.x;
    int e = gid >> 4, jg = gid & 15;
    float4 a = *(const float4*)(ea + (size_t)e * 4);
    float o[8];
    float4 bb0 = *(const float4*)(b1 + jg * 8);
    float4 bb1 = *(const float4*)(b1 + jg * 8 + 4);
    o[0] = bb0.x; o[1] = bb0.y; o[2] = bb0.z; o[3] = bb0.w;
    o[4] = bb1.x; o[5] = bb1.y; o[6] = bb1.z; o[7] = bb1.w;
#pragma unroll
    for (int k = 0; k < 4; k++) {
        float av = (&a.x)[k];
        float4 w0 = *(const float4*)(g_w1ct + k * 128 + jg * 8);
        float4 w1 = *(const float4*)(g_w1ct + k * 128 + jg * 8 + 4);
        fma8(o, av, w0, w1);
    }
    float* dst = g_eaw + (size_t)e * 128 + jg * 8;
#pragma unroll
    for (int j = 0; j < 8; j++) dst[j] = o[j];
}

__global__ void k_init() {
    int i = blockIdx.x * 256 + threadIdx.x;
    if (i < SSEG * SD) {
        g_c[i] = 0.f;
        g_nm[i] = 0.f;
        int s = i >> 6, d = i & 63;
        g_h[i] = (s >= NNODES && d == 0) ? 1.f : 0.f;
    }
    if (i < SSEG * 256) {
        int s = i >> 8, j = i & 255;
        g_p[i] = (s >= NNODES) ? g_wp[j] : 0.f;
    }
}

// =============== edge MLP via mma.sync (128 edges / CTA, 512 threads, N-split) ==========
#define SM_XH   0                    // 128*136*2 = 34816
#define SM_XL   34816
#define SM_W2H  69632
#define SM_W2L  104448
#define SM_W3H  139264               // 64*136*2 = 17408
#define SM_W3L  156672
#define SM_B2   174080               // 512B
#define SM_B3   174592               // 256B
#define SM_TOT  174848

__global__ __launch_bounds__(512, 1) void k_edge_mma(const int* __restrict__ row,
                                                     const int* __restrict__ col,
                                                     const float* __restrict__ b2,
                                                     const float* __restrict__ b3) {
    extern __shared__ char smem[];
    const uint32_t sb = smem_to_u32(smem);
    const int tid = threadIdx.x;
    const int wid = tid >> 5, lane = tid & 31;
    const int e0 = blockIdx.x * 128;
    float* b2s = (float*)(smem + SM_B2);
    float* b3s = (float*)(smem + SM_B3);

    if (tid < 128) b2s[tid] = b2[tid];
    else if (tid < 192) b3s[tid - 128] = b3[tid - 128];

    // weights: linear copy of pre-baked image
    {
        const float4* wsrc = (const float4*)g_wimg;
        float4* wdst = (float4*)(smem + SM_W2H);
        for (int i = tid; i < WIMG_TOT / 8; i += 512) wdst[i] = wsrc[i];
    }
    // gather + layer1 relu + bf16 hi/lo split into padded row-major X
    for (int u = tid; u < 128 * 32; u += 512) {
        int el = u >> 5, part = u & 31;
        int r = row[e0 + el], cn = col[e0 + el];
        int k = part * 4;
        float4 p1 = *(const float4*)(g_p + (size_t)r * 256 + k);
        float4 p2 = *(const float4*)(g_p + (size_t)cn * 256 + 128 + k);
        float4 z = *(const float4*)(g_eaw + (size_t)(e0 + el) * 128 + k);
        float v0 = fmaxf(p1.x + p2.x + z.x, 0.f), v1 = fmaxf(p1.y + p2.y + z.y, 0.f);
        float v2 = fmaxf(p1.z + p2.z + z.z, 0.f), v3 = fmaxf(p1.w + p2.w + z.w, 0.f);
        __nv_bfloat162 h0, l0, h1, l1;
        split2(v0, v1, h0, l0);
        split2(v2, v3, h1, l1);
        __nv_bfloat16* xh = (__nv_bfloat16*)(smem + SM_XH) + el * LDX + k;
        __nv_bfloat16* xl = (__nv_bfloat16*)(smem + SM_XL) + el * LDX + k;
        *(__nv_bfloat162*)(xh) = h0; *(__nv_bfloat162*)(xh + 2) = h1;
        *(__nv_bfloat162*)(xl) = l0; *(__nv_bfloat162*)(xl + 2) = l1;
    }
    __syncthreads();

    const int warpM = wid & 7, warpN = wid >> 3;
    const int m0 = warpM * 16;
    const int g = lane >> 2, t = lane & 3;
    const uint32_t aRowOff = (uint32_t)((m0 + (lane & 15)) * LDX + ((lane >> 4) << 3)) * 2;
    const uint32_t bRowSel = (uint32_t)(((lane & 7) * LDX + (((lane >> 3) & 1) << 3)) * 2);

    // ---------------- layer 2: this warp: 16 edges x 64 cols ----------------
    float c[8][4];
#pragma unroll
    for (int j = 0; j < 8; j++)
#pragma unroll
        for (int q = 0; q < 4; q++) c[j][q] = 0.f;

    const int n2base = warpN * 64;
    for (int k0 = 0; k0 < 128; k0 += 16) {
        uint32_t ah[4], al[4];
        ldsm_x4(ah[0], ah[1], ah[2], ah[3], sb + SM_XH + aRowOff + k0 * 2);
        ldsm_x4(al[0], al[1], al[2], al[3], sb + SM_XL + aRowOff + k0 * 2);
#pragma unroll
        for (int j = 0; j < 8; j++) {
            uint32_t bh[2], bl[2];
            uint32_t boff = bRowSel + (uint32_t)((n2base + j * 8) * LDX + k0) * 2;
            ldsm_x2(bh[0], bh[1], sb + SM_W2H + boff);
            ldsm_x2(bl[0], bl[1], sb + SM_W2L + boff);
            mma_bf16(c[j], ah, bh);
            mma_bf16(c[j], ah, bl);
            mma_bf16(c[j], al, bh);
        }
    }
    __syncthreads();   // all layer-2 X reads done before in-place overwrite

    // epilogue: bias+relu, re-split, overwrite X rows (this warp's 64 cols)
    {
        __nv_bfloat16* xh = (__nv_bfloat16*)(smem + SM_XH);
        __nv_bfloat16* xl = (__nv_bfloat16*)(smem + SM_XL);
#pragma unroll
        for (int j = 0; j < 8; j++) {
            int col0 = n2base + j * 8 + t * 2;
            float bb0 = b2s[col0], bb1 = b2s[col0 + 1];
#pragma unroll
            for (int rr = 0; rr < 2; rr++) {
                int erow = m0 + g + rr * 8;
                float x0 = fmaxf(c[j][2 * rr] + bb0, 0.f);
                float x1 = fmaxf(c[j][2 * rr + 1] + bb1, 0.f);
                __nv_bfloat162 hv, lv;
                split2(x0, x1, hv, lv);
                *(__nv_bfloat162*)(xh + erow * LDX + col0) = hv;
                *(__nv_bfloat162*)(xl + erow * LDX + col0) = lv;
            }
        }
    }
    __syncthreads();   // X2 fully written before layer-3 reads

    // ---------------- layer 3: this warp: 16 edges x 32 cols ----------------
    float c2[4][4];
#pragma unroll
    for (int j = 0; j < 4; j++)
#pragma unroll
        for (int q = 0; q < 4; q++) c2[j][q] = 0.f;

    const int n3base = warpN * 32;
    for (int k0 = 0; k0 < 128; k0 += 16) {
        uint32_t ah[4], al[4];
        ldsm_x4(ah[0], ah[1], ah[2], ah[3], sb + SM_XH + aRowOff + k0 * 2);
        ldsm_x4(al[0], al[1], al[2], al[3], sb + SM_XL + aRowOff + k0 * 2);
#pragma unroll
        for (int j = 0; j < 4; j++) {
            uint32_t bh[2], bl[2];
            uint32_t boff = bRowSel + (uint32_t)((n3base + j * 8) * LDX + k0) * 2;
            ldsm_x2(bh[0], bh[1], sb + SM_W3H + boff);
            ldsm_x2(bl[0], bl[1], sb + SM_W3L + boff);
            mma_bf16(c2[j], ah, bh);
            mma_bf16(c2[j], ah, bl);
            mma_bf16(c2[j], al, bh);
        }
    }
    // epilogue: bias + atomic scatter into nm[col]
    {
        int cA = col[e0 + m0 + g];
        int cB = col[e0 + m0 + g + 8];
        float* dA = g_nm + (size_t)cA * 64;
        float* dB = g_nm + (size_t)cB * 64;
#pragma unroll
        for (int j = 0; j < 4; j++) {
            int col0 = n3base + j * 8 + t * 2;
            float bb0 = b3s[col0], bb1 = b3s[col0 + 1];
            atomicAdd(dA + col0,     c2[j][0] + bb0);
            atomicAdd(dA + col0 + 1, c2[j][1] + bb1);
            atomicAdd(dB + col0,     c2[j][2] + bb0);
            atomicAdd(dB + col0 + 1, c2[j][3] + bb1);
        }
    }
}

// ====== LSTM via mma.sync (64 segments / CTA, 256 threads) + nm re-zero + projection =====
// smem overlay (bytes):
#define L_XH   0            // 64*136*2 = 17408
#define L_XL   17408        // -> 34816
#define L_WH   34816        // gates W hi: 256*136*2 = 69632 -> 104448
#define L_WL   104448       // -> 174080
#define L_G    34816        // OVERLAY: gates fp32 64*256*4 = 65536 -> 100352
#define L_PWH  100352       // OVERLAY: proj W hi 256*72*2 = 36864 -> 137216
#define L_PWL  137216       // -> 174080
#define L_BG   174080       // 1024B
#define L_TOT  175104

__global__ __launch_bounds__(256, 1) void k_lstm_mma() {
    extern __shared__ char smem[];
    const uint32_t sb = smem_to_u32(smem);
    const int tid = threadIdx.x;
    const int wid = tid >> 5, lane = tid & 31;
    const int s0 = blockIdx.x * 64;
    float* bgs = (float*)(smem + L_BG);

    bgs[tid] = g_bg[tid];

    // gates weights: linear copy (hi+lo, 139264B)
    {
        const float4* wsrc = (const float4*)g_wgimg;
        float4* wdst = (float4*)(smem + L_WH);
        for (int i = tid; i < 2 * 256 * LDX / 8; i += 256) wdst[i] = wsrc[i];
    }
    // gather X = [nm | h], bf16 split
    for (int u = tid; u < 64 * 32; u += 256) {
        int el = u >> 5, part = u & 31;
        int s = s0 + el;
        float4 v = make_float4(0.f, 0.f, 0.f, 0.f);
        if (s < SSEG) {
            const float* src = (part < 16) ? (g_nm + (size_t)s * SD + part * 4)
                                           : (g_h + (size_t)s * SD + (part - 16) * 4);
            v = *(const float4*)src;
        }
        int k = part * 4;
        __nv_bfloat162 h0, l0, h1, l1;
        split2(v.x, v.y, h0, l0);
        split2(v.z, v.w, h1, l1);
        __nv_bfloat16* xh = (__nv_bfloat16*)(smem + L_XH) + el * LDX + k;
        __nv_bfloat16* xl = (__nv_bfloat16*)(smem + L_XL) + el * LDX + k;
        *(__nv_bfloat162*)(xh) = h0; *(__nv_bfloat162*)(xh + 2) = h1;
        *(__nv_bfloat162*)(xl) = l0; *(__nv_bfloat162*)(xl + 2) = l1;
    }
    __syncthreads();

    const int warpM = wid & 3, warpN = wid >> 2;   // 4 M-groups x 2 N-halves
    const int m0 = warpM * 16;
    const int g = lane >> 2, t = lane & 3;
    const uint32_t aRowOff = (uint32_t)((m0 + (lane & 15)) * LDX + ((lane >> 4) << 3)) * 2;
    const uint32_t bRowSel = (uint32_t)(((lane & 7) * LDX + (((lane >> 3) & 1) << 3)) * 2);
    const int ncol0 = warpN * 128;

    // gates mma: 16 segs x 128 cols per warp
    float c[16][4];
#pragma unroll
    for (int j = 0; j < 16; j++)
#pragma unroll
        for (int q = 0; q < 4; q++) c[j][q] = 0.f;

    for (int k0 = 0; k0 < 128; k0 += 16) {
        uint32_t ah[4], al[4];
        ldsm_x4(ah[0], ah[1], ah[2], ah[3], sb + L_XH + aRowOff + k0 * 2);
        ldsm_x4(al[0], al[1], al[2], al[3], sb + L_XL + aRowOff + k0 * 2);
#pragma unroll
        for (int j = 0; j < 16; j++) {
            uint32_t bh[2], bl[2];
            uint32_t boff = bRowSel + (uint32_t)((ncol0 + j * 8) * LDX + k0) * 2;
            ldsm_x2(bh[0], bh[1], sb + L_WH + boff);
            ldsm_x2(bl[0], bl[1], sb + L_WL + boff);
            mma_bf16(c[j], ah, bh);
            mma_bf16(c[j], ah, bl);
            mma_bf16(c[j], al, bh);
        }
    }
    __syncthreads();   // all W/X reads done; W region reusable

    // write gates fp32 into overlay; copy proj weights; re-zero nm
    {
        float* sG = (float*)(smem + L_G);
#pragma unroll
        for (int j = 0; j < 16; j++) {
            int col0 = ncol0 + j * 8 + t * 2;
#pragma unroll
            for (int rr = 0; rr < 2; rr++) {
                int erow = m0 + g + rr * 8;
                *(float2*)(sG + erow * 256 + col0) =
                    make_float2(c[j][2 * rr], c[j][2 * rr + 1]);
            }
        }
        const float4* wsrc = (const float4*)g_wpimg;
        float4* wdst = (float4*)(smem + L_PWH);
        for (int i = tid; i < 2 * 256 * LDKP / 8; i += 256) wdst[i] = wsrc[i];
        for (int u = tid; u < 64 * 16; u += 256) {
            int el = u >> 4, part = u & 15;
            int s = s0 + el;
            if (s < SSEG)
                *(float4*)(g_nm + (size_t)s * SD + part * 4) = make_float4(0.f, 0.f, 0.f, 0.f);
        }
    }
    __syncthreads();

    // elementwise LSTM; write h/c to global; write hn bf16-split into X cols 0..63
    {
        const float* sG = (const float*)(smem + L_G);
        __nv_bfloat16* xh = (__nv_bfloat16*)(smem + L_XH);
        __nv_bfloat16* xl = (__nv_bfloat16*)(smem + L_XL);
        for (int u = tid; u < 64 * 32; u += 256) {   // 2 dims per unit
            int el = u >> 5, dp = (u & 31) * 2;
            int s = s0 + el;
            float hn0 = 0.f, hn1 = 0.f;
            if (s < SSEG) {
                float gi0 = sG[el * 256 + dp] + bgs[dp];
                float gi1 = sG[el * 256 + dp + 1] + bgs[dp + 1];
                float gf0 = sG[el * 256 + 64 + dp] + bgs[64 + dp];
                float gf1 = sG[el * 256 + 64 + dp + 1] + bgs[64 + dp + 1];
                float gg0 = sG[el * 256 + 128 + dp] + bgs[128 + dp];
                float gg1 = sG[el * 256 + 128 + dp + 1] + bgs[128 + dp + 1];
                float go0 = sG[el * 256 + 192 + dp] + bgs[192 + dp];
                float go1 = sG[el * 256 + 192 + dp + 1] + bgs[192 + dp + 1];
                float2 cc = *(float2*)(g_c + (size_t)s * SD + dp);
                float cn0 = sigm(gf0) * cc.x + sigm(gi0) * tanhf(gg0);
                float cn1 = sigm(gf1) * cc.y + sigm(gi1) * tanhf(gg1);
                *(float2*)(g_c + (size_t)s * SD + dp) = make_float2(cn0, cn1);
                hn0 = sigm(go0) * tanhf(cn0);
                hn1 = sigm(go1) * tanhf(cn1);
                *(float2*)(g_h + (size_t)s * SD + dp) = make_float2(hn0, hn1);
            }
            __nv_bfloat162 hv, lv;
            split2(hn0, hn1, hv, lv);
            *(__nv_bfloat162*)(xh + el * LDX + dp) = hv;
            *(__nv_bfloat162*)(xl + el * LDX + dp) = lv;
        }
    }
    __syncthreads();

    // projection mma: P[64 x 256] = hn(64x64) @ wp^T ; per warp 16 segs x 128 cols
    {
        float cp[16][4];
#pragma unroll
        for (int j = 0; j < 16; j++)
#pragma unroll
            for (int q = 0; q < 4; q++) cp[j][q] = 0.f;
        const uint32_t bRowSelP = (uint32_t)(((lane & 7) * LDKP + (((lane >> 3) & 1) << 3)) * 2);
        for (int k0 = 0; k0 < 64; k0 += 16) {
            uint32_t ah[4], al[4];
            ldsm_x4(ah[0], ah[1], ah[2], ah[3], sb + L_XH + aRowOff + k0 * 2);
            ldsm_x4(al[0], al[1], al[2], al[3], sb + L_XL + aRowOff + k0 * 2);
#pragma unroll
            for (int j = 0; j < 16; j++) {
                uint32_t bh[2], bl[2];
                uint32_t boff = bRowSelP + (uint32_t)((ncol0 + j * 8) * LDKP + k0) * 2;
                ldsm_x2(bh[0], bh[1], sb + L_PWH + boff);
                ldsm_x2(bl[0], bl[1], sb + L_PWL + boff);
                mma_bf16(cp[j], ah, bh);
                mma_bf16(cp[j], ah, bl);
                mma_bf16(cp[j], al, bh);
            }
        }
#pragma unroll
        for (int j = 0; j < 16; j++) {
            int col0 = ncol0 + j * 8 + t * 2;
#pragma unroll
            for (int rr = 0; rr < 2; rr++) {
                int s = s0 + m0 + g + rr * 8;
                if (s < SSEG)
                    *(float2*)(g_p + (size_t)s * 256 + col0) =
                        make_float2(cp[j][2 * rr], cp[j][2 * rr + 1]);
            }
        }
    }
}

// ---------------- readout MLP + softmax (scalar; runs once) ----------------
__global__ __launch_bounds__(128) void k_readout(const float* __restrict__ b1,
                                                 const float* __restrict__ b2,
                                                 const float* __restrict__ w3,
                                                 const float* __restrict__ b3,
                                                 float* __restrict__ out) {
    __shared__ float sX[32 * 68];
    __shared__ float sA[32 * 132];
    __shared__ float sB[32 * 132];
    const int tid = threadIdx.x;
    const int n0 = blockIdx.x * 32;

    for (int u = tid; u < 32 * 16; u += 128) {
        int el = u >> 4, part = u & 15;
        int n = n0 + el;
        float4 v = make_float4(0.f, 0.f, 0.f, 0.f);
        if (n < NNODES) v = *(const float4*)(g_h + (size_t)n * SD + part * 4);
        *(float4*)(sX + el * 68 + part * 4) = v;
    }
    __syncthreads();
    {
        const int te = tid & 7, tj = tid >> 3;
        float acc[4][8];
        tile_gemm<4, 8, SD, HM, 68>(sX, g_ro1t, te, tj, acc);
        float4 bb0 = *(const float4*)(b1 + tj * 8);
        float4 bb1 = *(const float4*)(b1 + tj * 8 + 4);
        float bv[8] = {bb0.x, bb0.y, bb0.z, bb0.w, bb1.x, bb1.y, bb1.z, bb1.w};
#pragma unroll
        for (int i = 0; i < 4; i++) {
            float* dst = sA + (te + i * 8) * 132 + tj * 8;
#pragma unroll
            for (int j = 0; j < 8; j++) dst[j] = fmaxf(acc[i][j] + bv[j], 0.f);
        }
    }
    __syncthreads();
    {
        const int te = tid & 7, tj = tid >> 3;
        float acc[4][8];
        tile_gemm<4, 8, HM, HM, 132>(sA, g_ro2t, te, tj, acc);
        float4 bb0 = *(const float4*)(b2 + tj * 8);
        float4 bb1 = *(const float4*)(b2 + tj * 8 + 4);
        float bv[8] = {bb0.x, bb0.y, bb0.z, bb0.w, bb1.x, bb1.y, bb1.z, bb1.w};
#pragma unroll
        for (int i = 0; i < 4; i++) {
            float* dst = sB + (te + i * 8) * 132 + tj * 8;
#pragma unroll
            for (int j = 0; j < 8; j++) dst[j] = fmaxf(acc[i][j] + bv[j], 0.f);
        }
    }
    __syncthreads();
    if (tid < 32) {
        int n = n0 + tid;
        if (n < NNODES) {
            float l0 = b3[0], l1 = b3[1];
            const float* x = sB + tid * 132;
#pragma unroll 4
            for (int k = 0; k < HM; k++) {
                l0 = fmaf(x[k], w3[k], l0);
                l1 = fmaf(x[k], w3[HM + k], l1);
            }
            float m = fmaxf(l0, l1);
            float e0 = expf(l0 - m), e1 = expf(l1 - m);
            float inv = 1.f / (e0 + e1);
            out[(size_t)n * 2 + 0] = e0 * inv;
            out[(size_t)n * 2 + 1] = e1 * inv;
        }
    }
}

// ---------------- launch ----------------
extern "C" void kernel_launch(void* const* d_in, const int* in_sizes, int n_in,
                              void* d_out, int out_size) {
    (void)out_size;
    int base = 3;
    if (n_in >= 21 && in_sizes[3] == 1 && in_sizes[4] == 1) base = 5;

    const int* row = (const int*)d_in[0];
    const int* col = (const int*)d_in[1];
    const float* ea = (const float*)d_in[2];
    const float* mp_w1 = (const float*)d_in[base + 0];
    const float* mp_b1 = (const float*)d_in[base + 1];
    const float* mp_w2 = (const float*)d_in[base + 2];
    const float* mp_b2 = (const float*)d_in[base + 3];
    const float* mp_w3 = (const float*)d_in[base + 4];
    const float* mp_b3 = (const float*)d_in[base + 5];
    const float* w_ih  = (const float*)d_in[base + 6];
    const float* w_hh  = (const float*)d_in[base + 7];
    const float* b_ih  = (const float*)d_in[base + 8];
    const float* b_hh  = (const float*)d_in[base + 9];
    const float* ro_w1 = (const float*)d_in[base + 10];
    const float* ro_b1 = (const float*)d_in[base + 11];
    const float* ro_w2 = (const float*)d_in[base + 12];
    const float* ro_b2 = (const float*)d_in[base + 13];
    const float* ro_w3 = (const float*)d_in[base + 14];
    const float* ro_b3 = (const float*)d_in[base + 15];
    float* out = (float*)d_out;

    cudaFuncSetAttribute(k_edge_mma, cudaFuncAttributeMaxDynamicSharedMemorySize, SM_TOT);
    cudaFuncSetAttribute(k_lstm_mma, cudaFuncAttributeMaxDynamicSharedMemorySize, L_TOT);

    k_prep<<<(PREP_TOTAL + 255) / 256, 256>>>(mp_w1, mp_w2, mp_w3, w_ih, w_hh,
                                              b_ih, b_hh, ro_w1, ro_w2);
    k_prep_pads<<<40, 256>>>();
    k_eaw<<<EEDGE * 16 / 256, 256>>>(ea, mp_b1);
    k_init<<<(SSEG * 256 + 255) / 256, 256>>>();

    for (int t = 0; t < NSTEPS; t++) {
        k_edge_mma<<<EEDGE / 128, 512, SM_TOT>>>(row, col, mp_b2, mp_b3);
        k_lstm_mma<<<(SSEG + 63) / 64, 256, L_TOT>>>();
    }

    k_readout<<<(NNODES + 31) / 32, 128>>>(ro_b1, ro_b2, ro_w3, ro_b3, out);
}

// round 17
// speedup vs baseline: 2.0522x; 1.3430x over previous
#include <cuda_runtime.h>
#include <cuda_bf16.h>
#include <math.h>
#include <stdint.h>

// Problem constants (fixed-shape problem)
#define NNODES 10000
#define NFACT  20000
#define SSEG   30000      // NNODES + NFACT
#define EEDGE  80000      // 4 * NFACT
#define SD     64         // STATE_DIM == MSG_DIM
#define HM     128        // HID_MSG == HID_RO
#define NSTEPS 10
#define WPAD   264
#define LDX    136        // padded bf16 row stride (272B = 16*17: ldmatrix-aligned, conflict-free)
#define LDKP   72         // proj-weight padded k-stride (144B = 16*9: ldmatrix-aligned)

// ---------------- persistent device scratch (no allocation allowed) ----------------
__device__ float g_h[SSEG * SD];
__device__ float g_c[SSEG * SD];
__device__ float g_nm[SSEG * SD];
__device__ float g_p[SSEG * 256];               // [P1(128) | P2(128)] per segment
__device__ float g_eaw[EEDGE * HM];             // W1c @ edge_attr + b1 (step-invariant)
__device__ __align__(16) float g_wp[SD * 256 + WPAD];         // [k=64][j=256]
__device__ __align__(16) float g_w1ct[4 * HM];                // [k=4][j=128] = W1c^T
__device__ __align__(16) float g_bg[4 * SD];                  // b_ih + b_hh
__device__ __align__(16) float g_ro1t[SD * HM + WPAD];        // [64][128]  = ro_w1^T
__device__ __align__(16) float g_ro2t[HM * HM + WPAD];        // [128][128] = ro_w2^T
// bf16 hi/lo edge-weight image, padded [n][LDX]:
#define WIMG_W2H 0
#define WIMG_W2L 17408
#define WIMG_W3H 34816
#define WIMG_W3L 43520
#define WIMG_TOT 52224
__device__ __align__(16) __nv_bfloat16 g_wimg[WIMG_TOT];
// LSTM gates weight image [n=256][k=LDX pad]: hi at 0, lo at 256*LDX
__device__ __align__(16) __nv_bfloat16 g_wgimg[2 * 256 * LDX];
// projection weight image [n=256][k=LDKP pad]: hi at 0, lo at 256*LDKP
__device__ __align__(16) __nv_bfloat16 g_wpimg[2 * 256 * LDKP];

__device__ __forceinline__ float sigm(float x) { return 1.f / (1.f + __expf(-x)); }

__device__ __forceinline__ uint32_t smem_to_u32(const void* p) {
    uint32_t a;
    asm("{ .reg .u64 t; cvta.to.shared.u64 t, %1; cvt.u32.u64 %0, t; }" : "=r"(a) : "l"(p));
    return a;
}

// ---- cp.async (LDGSTS, sm_80+) ----
__device__ __forceinline__ void cp_async16(uint32_t dst_smem, const void* src) {
    asm volatile("cp.async.cg.shared.global [%0], [%1], 16;" :: "r"(dst_smem), "l"(src));
}
#define CP_ASYNC_WAIT() asm volatile("cp.async.commit_group;\n\tcp.async.wait_group 0;" ::: "memory")

// ---- legacy tensor-core primitives (sm_80+; compile for plain sm_100) ----
__device__ __forceinline__ void ldsm_x4(uint32_t& r0, uint32_t& r1, uint32_t& r2, uint32_t& r3,
                                        uint32_t addr) {
    asm volatile("ldmatrix.sync.aligned.m8n8.x4.shared.b16 {%0,%1,%2,%3}, [%4];"
                 : "=r"(r0), "=r"(r1), "=r"(r2), "=r"(r3) : "r"(addr));
}
__device__ __forceinline__ void ldsm_x2(uint32_t& r0, uint32_t& r1, uint32_t addr) {
    asm volatile("ldmatrix.sync.aligned.m8n8.x2.shared.b16 {%0,%1}, [%2];"
                 : "=r"(r0), "=r"(r1) : "r"(addr));
}
__device__ __forceinline__ void mma_bf16(float* c, const uint32_t* a, const uint32_t* b) {
    asm volatile("mma.sync.aligned.m16n8k16.row.col.f32.bf16.bf16.f32 "
                 "{%0,%1,%2,%3}, {%4,%5,%6,%7}, {%8,%9}, {%0,%1,%2,%3};"
                 : "+f"(c[0]), "+f"(c[1]), "+f"(c[2]), "+f"(c[3])
                 : "r"(a[0]), "r"(a[1]), "r"(a[2]), "r"(a[3]), "r"(b[0]), "r"(b[1]));
}
__device__ __forceinline__ void split2(float x0, float x1, __nv_bfloat162& hv, __nv_bfloat162& lv) {
    __nv_bfloat16 h0 = __float2bfloat16_rn(x0), h1 = __float2bfloat16_rn(x1);
    hv.x = h0; hv.y = h1;
    lv.x = __float2bfloat16_rn(x0 - __bfloat162float(h0));
    lv.y = __float2bfloat16_rn(x1 - __bfloat162float(h1));
}

// ---- scalar fp32 GEMM (for readout) ----
__device__ __forceinline__ void fma8(float* a, float x, const float4 w0, const float4 w1) {
    a[0] = fmaf(x, w0.x, a[0]); a[1] = fmaf(x, w0.y, a[1]);
    a[2] = fmaf(x, w0.z, a[2]); a[3] = fmaf(x, w0.w, a[3]);
    a[4] = fmaf(x, w1.x, a[4]); a[5] = fmaf(x, w1.y, a[5]);
    a[6] = fmaf(x, w1.z, a[6]); a[7] = fmaf(x, w1.w, a[7]);
}
template <int NE, int NT, int K, int NJ, int SX>
__device__ __forceinline__ void tile_gemm(const float* sIn, const float* __restrict__ Wt,
                                          int te, int tj, float acc[][8]) {
#pragma unroll
    for (int i = 0; i < NE; i++)
#pragma unroll
        for (int j = 0; j < 8; j++) acc[i][j] = 0.f;
    const float* wbase = Wt + tj * 8;
#pragma unroll 2
    for (int k = 0; k < K; k += 4) {
        float4 xv[NE];
#pragma unroll
        for (int i = 0; i < NE; i++)
            xv[i] = *(const float4*)(sIn + (te + i * NT) * SX + k);
#pragma unroll
        for (int kk = 0; kk < 4; kk++) {
            float4 w0 = *(const float4*)(wbase + (k + kk) * NJ);
            float4 w1 = *(const float4*)(wbase + (k + kk) * NJ + 4);
#pragma unroll
            for (int i = 0; i < NE; i++)
                fma8(acc[i], (&xv[i].x)[kk], w0, w1);
        }
    }
}

// ---------------- prep: transpose/split weights, bake bf16 images ----------------
#define PREP_TOTAL (16384 + 512 + 16384 + 8192 + 32768 + 16384 + 256 + 8192 + 16384)
__global__ void k_prep(const float* __restrict__ w1, const float* __restrict__ w2,
                       const float* __restrict__ w3, const float* __restrict__ wih,
                       const float* __restrict__ whh, const float* __restrict__ bih,
                       const float* __restrict__ bhh, const float* __restrict__ r1,
                       const float* __restrict__ r2) {
    int i = blockIdx.x * 256 + threadIdx.x;
    if (i < 16384) {
        int j = i & 255, k = i >> 8;
        g_wp[k * 256 + j] = (j < 128) ? w1[j * 132 + k] : w1[(j - 128) * 132 + 64 + k];
        return;
    }
    i -= 16384;
    if (i < 512)   { int k = i >> 7, j = i & 127; g_w1ct[k * 128 + j] = w1[j * 132 + 128 + k]; return; }
    i -= 512;
    if (i < 16384) {
        int n = i >> 7, k = i & 127;
        float w = w2[n * 128 + k];
        __nv_bfloat16 h = __float2bfloat16_rn(w);
        g_wimg[WIMG_W2H + n * LDX + k] = h;
        g_wimg[WIMG_W2L + n * LDX + k] = __float2bfloat16_rn(w - __bfloat162float(h));
        return;
    }
    i -= 16384;
    if (i < 8192)  {
        int n = i >> 7, k = i & 127;
        float w = w3[n * 128 + k];
        __nv_bfloat16 h = __float2bfloat16_rn(w);
        g_wimg[WIMG_W3H + n * LDX + k] = h;
        g_wimg[WIMG_W3L + n * LDX + k] = __float2bfloat16_rn(w - __bfloat162float(h));
        return;
    }
    i -= 8192;
    if (i < 32768) {
        int n = i >> 7, k = i & 127;
        float w = (k < 64) ? wih[n * 64 + k] : whh[n * 64 + (k - 64)];
        __nv_bfloat16 h = __float2bfloat16_rn(w);
        g_wgimg[n * LDX + k] = h;
        g_wgimg[256 * LDX + n * LDX + k] = __float2bfloat16_rn(w - __bfloat162float(h));
        return;
    }
    i -= 32768;
    if (i < 16384) {
        int n = i >> 6, k = i & 63;
        float w = (n < 128) ? w1[n * 132 + k] : w1[(n - 128) * 132 + 64 + k];
        __nv_bfloat16 h = __float2bfloat16_rn(w);
        g_wpimg[n * LDKP + k] = h;
        g_wpimg[256 * LDKP + n * LDKP + k] = __float2bfloat16_rn(w - __bfloat162float(h));
        return;
    }
    i -= 16384;
    if (i < 256)   { g_bg[i] = bih[i] + bhh[i]; return; }
    i -= 256;
    if (i < 8192)  { int j = i / 64, k = i % 64; g_ro1t[k * 128 + j] = r1[i]; return; }
    i -= 8192;
    if (i < 16384) { int j = i / 128, k = i % 128; g_ro2t[k * 128 + j] = r2[i]; return; }
}

// zero the k-pad columns of the bf16 images so mma reads 0s
__global__ void k_prep_pads() {
    int i = blockIdx.x * 256 + threadIdx.x;
    if (i < 128 * 8) { int n = i >> 3, k = 128 + (i & 7); g_wimg[WIMG_W2H + n * LDX + k] = __nv_bfloat16(0.f); return; }
    i -= 1024;
    if (i < 128 * 8) { int n = i >> 3, k = 128 + (i & 7); g_wimg[WIMG_W2L + n * LDX + k] = __nv_bfloat16(0.f); return; }
    i -= 1024;
    if (i < 64 * 8)  { int n = i >> 3, k = 128 + (i & 7); g_wimg[WIMG_W3H + n * LDX + k] = __nv_bfloat16(0.f); return; }
    i -= 512;
    if (i < 64 * 8)  { int n = i >> 3, k = 128 + (i & 7); g_wimg[WIMG_W3L + n * LDX + k] = __nv_bfloat16(0.f); return; }
    i -= 512;
    if (i < 256 * 8) { int n = i >> 3, k = 128 + (i & 7); g_wgimg[n * LDX + k] = __nv_bfloat16(0.f); return; }
    i -= 2048;
    if (i < 256 * 8) { int n = i >> 3, k = 128 + (i & 7); g_wgimg[256 * LDX + n * LDX + k] = __nv_bfloat16(0.f); return; }
    i -= 2048;
    if (i < 256 * 8) { int n = i >> 3, k = 64 + (i & 7); g_wpimg[n * LDKP + k] = __nv_bfloat16(0.f); return; }
    i -= 2048;
    if (i < 256 * 8) { int n = i >> 3, k = 64 + (i & 7); g_wpimg[256 * LDKP + n * LDKP + k] = __nv_bfloat16(0.f); return; }
}

// eaw[e][j] = b1[j] + sum_{k<4} ea[e][k] * W1c[j][k]
__global__ void k_eaw(const float* __restrict__ ea, const float* __restrict__ b1) {
    int gid = blockIdx.x * 256 + threadIdx.x;
    int e = gid >> 4, jg = gid & 15;
    float4 a = *(const float4*)(ea + (size_t)e * 4);
    float o[8];
    float4 bb0 = *(const float4*)(b1 + jg * 8);
    float4 bb1 = *(const float4*)(b1 + jg * 8 + 4);
    o[0] = bb0.x; o[1] = bb0.y; o[2] = bb0.z; o[3] = bb0.w;
    o[4] = bb1.x; o[5] = bb1.y; o[6] = bb1.z; o[7] = bb1.w;
#pragma unroll
    for (int k = 0; k < 4; k++) {
        float av = (&a.x)[k];
        float4 w0 = *(const float4*)(g_w1ct + k * 128 + jg * 8);
        float4 w1 = *(const float4*)(g_w1ct + k * 128 + jg * 8 + 4);
        fma8(o, av, w0, w1);
    }
    float* dst = g_eaw + (size_t)e * 128 + jg * 8;
#pragma unroll
    for (int j = 0; j < 8; j++) dst[j] = o[j];
}

__global__ void k_init() {
    int i = blockIdx.x * 256 + threadIdx.x;
    if (i < SSEG * SD) {
        g_c[i] = 0.f;
        g_nm[i] = 0.f;
        int s = i >> 6, d = i & 63;
        g_h[i] = (s >= NNODES && d == 0) ? 1.f : 0.f;
    }
    if (i < SSEG * 256) {
        int s = i >> 8, j = i & 255;
        g_p[i] = (s >= NNODES) ? g_wp[j] : 0.f;
    }
}

// =============== edge MLP via mma.sync (128 edges / CTA, 512 threads, N-split) ==========
#define SM_XH   0                    // 128*136*2 = 34816
#define SM_XL   34816
#define SM_W2H  69632
#define SM_W2L  104448
#define SM_W3H  139264
#define SM_W3L  156672
#define SM_B2   174080
#define SM_B3   174592
#define SM_TOT  174848

__global__ __launch_bounds__(512, 1) void k_edge_mma(const int* __restrict__ row,
                                                     const int* __restrict__ col,
                                                     const float* __restrict__ b2,
                                                     const float* __restrict__ b3) {
    extern __shared__ char smem[];
    const uint32_t sb = smem_to_u32(smem);
    const int tid = threadIdx.x;
    const int wid = tid >> 5, lane = tid & 31;
    const int e0 = blockIdx.x * 128;
    float* b2s = (float*)(smem + SM_B2);
    float* b3s = (float*)(smem + SM_B3);

    if (tid < 128) b2s[tid] = b2[tid];
    else if (tid < 192) b3s[tid - 128] = b3[tid - 128];

    // weights: async copy of pre-baked image (overlapped with gather below)
    {
        const float4* wsrc = (const float4*)g_wimg;
        for (int i = tid; i < WIMG_TOT / 8; i += 512)
            cp_async16(sb + SM_W2H + i * 16, wsrc + i);
    }
    // gather + layer1 relu + bf16 hi/lo split into padded row-major X
    for (int u = tid; u < 128 * 32; u += 512) {
        int el = u >> 5, part = u & 31;
        int r = row[e0 + el], cn = col[e0 + el];
        int k = part * 4;
        float4 p1 = *(const float4*)(g_p + (size_t)r * 256 + k);
        float4 p2 = *(const float4*)(g_p + (size_t)cn * 256 + 128 + k);
        float4 z = *(const float4*)(g_eaw + (size_t)(e0 + el) * 128 + k);
        float v0 = fmaxf(p1.x + p2.x + z.x, 0.f), v1 = fmaxf(p1.y + p2.y + z.y, 0.f);
        float v2 = fmaxf(p1.z + p2.z + z.z, 0.f), v3 = fmaxf(p1.w + p2.w + z.w, 0.f);
        __nv_bfloat162 h0, l0, h1, l1;
        split2(v0, v1, h0, l0);
        split2(v2, v3, h1, l1);
        __nv_bfloat16* xh = (__nv_bfloat16*)(smem + SM_XH) + el * LDX + k;
        __nv_bfloat16* xl = (__nv_bfloat16*)(smem + SM_XL) + el * LDX + k;
        *(__nv_bfloat162*)(xh) = h0; *(__nv_bfloat162*)(xh + 2) = h1;
        *(__nv_bfloat162*)(xl) = l0; *(__nv_bfloat162*)(xl + 2) = l1;
    }
    CP_ASYNC_WAIT();
    __syncthreads();

    const int warpM = wid & 7, warpN = wid >> 3;
    const int m0 = warpM * 16;
    const int g = lane >> 2, t = lane & 3;
    const uint32_t aRowOff = (uint32_t)((m0 + (lane & 15)) * LDX + ((lane >> 4) << 3)) * 2;
    const uint32_t bRowSel = (uint32_t)(((lane & 7) * LDX + (((lane >> 3) & 1) << 3)) * 2);

    // ---------------- layer 2: this warp: 16 edges x 64 cols ----------------
    float c[8][4];
#pragma unroll
    for (int j = 0; j < 8; j++)
#pragma unroll
        for (int q = 0; q < 4; q++) c[j][q] = 0.f;

    const int n2base = warpN * 64;
    for (int k0 = 0; k0 < 128; k0 += 16) {
        uint32_t ah[4], al[4];
        ldsm_x4(ah[0], ah[1], ah[2], ah[3], sb + SM_XH + aRowOff + k0 * 2);
        ldsm_x4(al[0], al[1], al[2], al[3], sb + SM_XL + aRowOff + k0 * 2);
#pragma unroll
        for (int j = 0; j < 8; j++) {
            uint32_t bh[2], bl[2];
            uint32_t boff = bRowSel + (uint32_t)((n2base + j * 8) * LDX + k0) * 2;
            ldsm_x2(bh[0], bh[1], sb + SM_W2H + boff);
            ldsm_x2(bl[0], bl[1], sb + SM_W2L + boff);
            mma_bf16(c[j], ah, bh);
            mma_bf16(c[j], ah, bl);
            mma_bf16(c[j], al, bh);
        }
    }
    __syncthreads();

    // epilogue: bias+relu, re-split, overwrite X rows (this warp's 64 cols)
    {
        __nv_bfloat16* xh = (__nv_bfloat16*)(smem + SM_XH);
        __nv_bfloat16* xl = (__nv_bfloat16*)(smem + SM_XL);
#pragma unroll
        for (int j = 0; j < 8; j++) {
            int col0 = n2base + j * 8 + t * 2;
            float bb0 = b2s[col0], bb1 = b2s[col0 + 1];
#pragma unroll
            for (int rr = 0; rr < 2; rr++) {
                int erow = m0 + g + rr * 8;
                float x0 = fmaxf(c[j][2 * rr] + bb0, 0.f);
                float x1 = fmaxf(c[j][2 * rr + 1] + bb1, 0.f);
                __nv_bfloat162 hv, lv;
                split2(x0, x1, hv, lv);
                *(__nv_bfloat162*)(xh + erow * LDX + col0) = hv;
                *(__nv_bfloat162*)(xl + erow * LDX + col0) = lv;
            }
        }
    }
    __syncthreads();

    // ---------------- layer 3: this warp: 16 edges x 32 cols ----------------
    float c2[4][4];
#pragma unroll
    for (int j = 0; j < 4; j++)
#pragma unroll
        for (int q = 0; q < 4; q++) c2[j][q] = 0.f;

    const int n3base = warpN * 32;
    for (int k0 = 0; k0 < 128; k0 += 16) {
        uint32_t ah[4], al[4];
        ldsm_x4(ah[0], ah[1], ah[2], ah[3], sb + SM_XH + aRowOff + k0 * 2);
        ldsm_x4(al[0], al[1], al[2], al[3], sb + SM_XL + aRowOff + k0 * 2);
#pragma unroll
        for (int j = 0; j < 4; j++) {
            uint32_t bh[2], bl[2];
            uint32_t boff = bRowSel + (uint32_t)((n3base + j * 8) * LDX + k0) * 2;
            ldsm_x2(bh[0], bh[1], sb + SM_W3H + boff);
            ldsm_x2(bl[0], bl[1], sb + SM_W3L + boff);
            mma_bf16(c2[j], ah, bh);
            mma_bf16(c2[j], ah, bl);
            mma_bf16(c2[j], al, bh);
        }
    }
    // epilogue: bias + atomic scatter into nm[col]
    {
        int cA = col[e0 + m0 + g];
        int cB = col[e0 + m0 + g + 8];
        float* dA = g_nm + (size_t)cA * 64;
        float* dB = g_nm + (size_t)cB * 64;
#pragma unroll
        for (int j = 0; j < 4; j++) {
            int col0 = n3base + j * 8 + t * 2;
            float bb0 = b3s[col0], bb1 = b3s[col0 + 1];
            atomicAdd(dA + col0,     c2[j][0] + bb0);
            atomicAdd(dA + col0 + 1, c2[j][1] + bb1);
            atomicAdd(dB + col0,     c2[j][2] + bb0);
            atomicAdd(dB + col0 + 1, c2[j][3] + bb1);
        }
    }
}

// ====== LSTM via mma.sync (64 segments / CTA, 512 threads) + nm re-zero + projection =====
#define L_XH   0            // 64*136*2 = 17408
#define L_XL   17408        // -> 34816
#define L_WH   34816        // gates W hi -> 104448
#define L_WL   104448       // -> 174080
#define L_G    34816        // OVERLAY: gates fp32 64*256*4 -> 100352
#define L_PWH  100352       // OVERLAY: proj W hi 256*72*2 = 36864 -> 137216
#define L_PWL  137216       // -> 174080
#define L_BG   174080       // 1024B
#define L_TOT  175104

__global__ __launch_bounds__(512, 1) void k_lstm_mma() {
    extern __shared__ char smem[];
    const uint32_t sb = smem_to_u32(smem);
    const int tid = threadIdx.x;
    const int wid = tid >> 5, lane = tid & 31;
    const int s0 = blockIdx.x * 64;
    float* bgs = (float*)(smem + L_BG);

    if (tid < 256) bgs[tid] = g_bg[tid];

    // gates weights: async copy (overlapped with gather below)
    {
        const float4* wsrc = (const float4*)g_wgimg;
        for (int i = tid; i < 2 * 256 * LDX / 8; i += 512)
            cp_async16(sb + L_WH + i * 16, wsrc + i);
    }
    // gather X = [nm | h], bf16 split
    for (int u = tid; u < 64 * 32; u += 512) {
        int el = u >> 5, part = u & 31;
        int s = s0 + el;
        float4 v = make_float4(0.f, 0.f, 0.f, 0.f);
        if (s < SSEG) {
            const float* src = (part < 16) ? (g_nm + (size_t)s * SD + part * 4)
                                           : (g_h + (size_t)s * SD + (part - 16) * 4);
            v = *(const float4*)src;
        }
        int k = part * 4;
        __nv_bfloat162 h0, l0, h1, l1;
        split2(v.x, v.y, h0, l0);
        split2(v.z, v.w, h1, l1);
        __nv_bfloat16* xh = (__nv_bfloat16*)(smem + L_XH) + el * LDX + k;
        __nv_bfloat16* xl = (__nv_bfloat16*)(smem + L_XL) + el * LDX + k;
        *(__nv_bfloat162*)(xh) = h0; *(__nv_bfloat162*)(xh + 2) = h1;
        *(__nv_bfloat162*)(xl) = l0; *(__nv_bfloat162*)(xl + 2) = l1;
    }
    CP_ASYNC_WAIT();
    __syncthreads();

    const int warpM = wid & 3, warpN = wid >> 2;   // 4 M-groups x 4 N-quarters
    const int m0 = warpM * 16;
    const int g = lane >> 2, t = lane & 3;
    const uint32_t aRowOff = (uint32_t)((m0 + (lane & 15)) * LDX + ((lane >> 4) << 3)) * 2;
    const uint32_t bRowSel = (uint32_t)(((lane & 7) * LDX + (((lane >> 3) & 1) << 3)) * 2);
    const int ncol0 = warpN * 64;

    // gates mma: 16 segs x 64 cols per warp
    float c[8][4];
#pragma unroll
    for (int j = 0; j < 8; j++)
#pragma unroll
        for (int q = 0; q < 4; q++) c[j][q] = 0.f;

    for (int k0 = 0; k0 < 128; k0 += 16) {
        uint32_t ah[4], al[4];
        ldsm_x4(ah[0], ah[1], ah[2], ah[3], sb + L_XH + aRowOff + k0 * 2);
        ldsm_x4(al[0], al[1], al[2], al[3], sb + L_XL + aRowOff + k0 * 2);
#pragma unroll
        for (int j = 0; j < 8; j++) {
            uint32_t bh[2], bl[2];
            uint32_t boff = bRowSel + (uint32_t)((ncol0 + j * 8) * LDX + k0) * 2;
            ldsm_x2(bh[0], bh[1], sb + L_WH + boff);
            ldsm_x2(bl[0], bl[1], sb + L_WL + boff);
            mma_bf16(c[j], ah, bh);
            mma_bf16(c[j], ah, bl);
            mma_bf16(c[j], al, bh);
        }
    }
    __syncthreads();   // all W/X reads done; W region reusable

    // write gates fp32 into overlay; async-copy proj weights; re-zero nm
    {
        float* sG = (float*)(smem + L_G);
#pragma unroll
        for (int j = 0; j < 8; j++) {
            int col0 = ncol0 + j * 8 + t * 2;
#pragma unroll
            for (int rr = 0; rr < 2; rr++) {
                int erow = m0 + g + rr * 8;
                *(float2*)(sG + erow * 256 + col0) =
                    make_float2(c[j][2 * rr], c[j][2 * rr + 1]);
            }
        }
        const float4* wsrc = (const float4*)g_wpimg;
        for (int i = tid; i < 2 * 256 * LDKP / 8; i += 512)
            cp_async16(sb + L_PWH + i * 16, wsrc + i);
        for (int u = tid; u < 64 * 16; u += 512) {
            int el = u >> 4, part = u & 15;
            int s = s0 + el;
            if (s < SSEG)
                *(float4*)(g_nm + (size_t)s * SD + part * 4) = make_float4(0.f, 0.f, 0.f, 0.f);
        }
    }
    CP_ASYNC_WAIT();
    __syncthreads();

    // elementwise LSTM; write h/c to global; write hn bf16-split into X cols 0..63
    {
        const float* sG = (const float*)(smem + L_G);
        __nv_bfloat16* xh = (__nv_bfloat16*)(smem + L_XH);
        __nv_bfloat16* xl = (__nv_bfloat16*)(smem + L_XL);
        for (int u = tid; u < 64 * 32; u += 512) {   // 2 dims per unit
            int el = u >> 5, dp = (u & 31) * 2;
            int s = s0 + el;
            float hn0 = 0.f, hn1 = 0.f;
            if (s < SSEG) {
                float gi0 = sG[el * 256 + dp] + bgs[dp];
                float gi1 = sG[el * 256 + dp + 1] + bgs[dp + 1];
                float gf0 = sG[el * 256 + 64 + dp] + bgs[64 + dp];
                float gf1 = sG[el * 256 + 64 + dp + 1] + bgs[64 + dp + 1];
                float gg0 = sG[el * 256 + 128 + dp] + bgs[128 + dp];
                float gg1 = sG[el * 256 + 128 + dp + 1] + bgs[128 + dp + 1];
                float go0 = sG[el * 256 + 192 + dp] + bgs[192 + dp];
                float go1 = sG[el * 256 + 192 + dp + 1] + bgs[192 + dp + 1];
                float2 cc = *(float2*)(g_c + (size_t)s * SD + dp);
                float cn0 = sigm(gf0) * cc.x + sigm(gi0) * tanhf(gg0);
                float cn1 = sigm(gf1) * cc.y + sigm(gi1) * tanhf(gg1);
                *(float2*)(g_c + (size_t)s * SD + dp) = make_float2(cn0, cn1);
                hn0 = sigm(go0) * tanhf(cn0);
                hn1 = sigm(go1) * tanhf(cn1);
                *(float2*)(g_h + (size_t)s * SD + dp) = make_float2(hn0, hn1);
            }
            __nv_bfloat162 hv, lv;
            split2(hn0, hn1, hv, lv);
            *(__nv_bfloat162*)(xh + el * LDX + dp) = hv;
            *(__nv_bfloat162*)(xl + el * LDX + dp) = lv;
        }
    }
    __syncthreads();

    // projection mma: P[64 x 256] = hn(64x64) @ wp^T ; per warp 16 segs x 64 cols
    {
        float cp[8][4];
#pragma unroll
        for (int j = 0; j < 8; j++)
#pragma unroll
            for (int q = 0; q < 4; q++) cp[j][q] = 0.f;
        const uint32_t bRowSelP = (uint32_t)(((lane & 7) * LDKP + (((lane >> 3) & 1) << 3)) * 2);
        for (int k0 = 0; k0 < 64; k0 += 16) {
            uint32_t ah[4], al[4];
            ldsm_x4(ah[0], ah[1], ah[2], ah[3], sb + L_XH + aRowOff + k0 * 2);
            ldsm_x4(al[0], al[1], al[2], al[3], sb + L_XL + aRowOff + k0 * 2);
#pragma unroll
            for (int j = 0; j < 8; j++) {
                uint32_t bh[2], bl[2];
                uint32_t boff = bRowSelP + (uint32_t)((ncol0 + j * 8) * LDKP + k0) * 2;
                ldsm_x2(bh[0], bh[1], sb + L_PWH + boff);
                ldsm_x2(bl[0], bl[1], sb + L_PWL + boff);
                mma_bf16(cp[j], ah, bh);
                mma_bf16(cp[j], ah, bl);
                mma_bf16(cp[j], al, bh);
            }
        }
#pragma unroll
        for (int j = 0; j < 8; j++) {
            int col0 = ncol0 + j * 8 + t * 2;
#pragma unroll
            for (int rr = 0; rr < 2; rr++) {
                int s = s0 + m0 + g + rr * 8;
                if (s < SSEG)
                    *(float2*)(g_p + (size_t)s * 256 + col0) =
                        make_float2(cp[j][2 * rr], cp[j][2 * rr + 1]);
            }
        }
    }
}

// ---------------- readout MLP + softmax (scalar; runs once) ----------------
__global__ __launch_bounds__(128) void k_readout(const float* __restrict__ b1,
                                                 const float* __restrict__ b2,
                                                 const float* __restrict__ w3,
                                                 const float* __restrict__ b3,
                                                 float* __restrict__ out) {
    __shared__ float sX[32 * 68];
    __shared__ float sA[32 * 132];
    __shared__ float sB[32 * 132];
    const int tid = threadIdx.x;
    const int n0 = blockIdx.x * 32;

    for (int u = tid; u < 32 * 16; u += 128) {
        int el = u >> 4, part = u & 15;
        int n = n0 + el;
        float4 v = make_float4(0.f, 0.f, 0.f, 0.f);
        if (n < NNODES) v = *(const float4*)(g_h + (size_t)n * SD + part * 4);
        *(float4*)(sX + el * 68 + part * 4) = v;
    }
    __syncthreads();
    {
        const int te = tid & 7, tj = tid >> 3;
        float acc[4][8];
        tile_gemm<4, 8, SD, HM, 68>(sX, g_ro1t, te, tj, acc);
        float4 bb0 = *(const float4*)(b1 + tj * 8);
        float4 bb1 = *(const float4*)(b1 + tj * 8 + 4);
        float bv[8] = {bb0.x, bb0.y, bb0.z, bb0.w, bb1.x, bb1.y, bb1.z, bb1.w};
#pragma unroll
        for (int i = 0; i < 4; i++) {
            float* dst = sA + (te + i * 8) * 132 + tj * 8;
#pragma unroll
            for (int j = 0; j < 8; j++) dst[j] = fmaxf(acc[i][j] + bv[j], 0.f);
        }
    }
    __syncthreads();
    {
        const int te = tid & 7, tj = tid >> 3;
        float acc[4][8];
        tile_gemm<4, 8, HM, HM, 132>(sA, g_ro2t, te, tj, acc);
        float4 bb0 = *(const float4*)(b2 + tj * 8);
        float4 bb1 = *(const float4*)(b2 + tj * 8 + 4);
        float bv[8] = {bb0.x, bb0.y, bb0.z, bb0.w, bb1.x, bb1.y, bb1.z, bb1.w};
#pragma unroll
        for (int i = 0; i < 4; i++) {
            float* dst = sB + (te + i * 8) * 132 + tj * 8;
#pragma unroll
            for (int j = 0; j < 8; j++) dst[j] = fmaxf(acc[i][j] + bv[j], 0.f);
        }
    }
    __syncthreads();
    if (tid < 32) {
        int n = n0 + tid;
        if (n < NNODES) {
            float l0 = b3[0], l1 = b3[1];
            const float* x = sB + tid * 132;
#pragma unroll 4
            for (int k = 0; k < HM; k++) {
                l0 = fmaf(x[k], w3[k], l0);
                l1 = fmaf(x[k], w3[HM + k], l1);
            }
            float m = fmaxf(l0, l1);
            float e0 = expf(l0 - m), e1 = expf(l1 - m);
            float inv = 1.f / (e0 + e1);
            out[(size_t)n * 2 + 0] = e0 * inv;
            out[(size_t)n * 2 + 1] = e1 * inv;
        }
    }
}

// ---------------- launch ----------------
extern "C" void kernel_launch(void* const* d_in, const int* in_sizes, int n_in,
                              void* d_out, int out_size) {
    (void)out_size;
    int base = 3;
    if (n_in >= 21 && in_sizes[3] == 1 && in_sizes[4] == 1) base = 5;

    const int* row = (const int*)d_in[0];
    const int* col = (const int*)d_in[1];
    const float* ea = (const float*)d_in[2];
    const float* mp_w1 = (const float*)d_in[base + 0];
    const float* mp_b1 = (const float*)d_in[base + 1];
    const float* mp_w2 = (const float*)d_in[base + 2];
    const float* mp_b2 = (const float*)d_in[base + 3];
    const float* mp_w3 = (const float*)d_in[base + 4];
    const float* mp_b3 = (const float*)d_in[base + 5];
    const float* w_ih  = (const float*)d_in[base + 6];
    const float* w_hh  = (const float*)d_in[base + 7];
    const float* b_ih  = (const float*)d_in[base + 8];
    const float* b_hh  = (const float*)d_in[base + 9];
    const float* ro_w1 = (const float*)d_in[base + 10];
    const float* ro_b1 = (const float*)d_in[base + 11];
    const float* ro_w2 = (const float*)d_in[base + 12];
    const float* ro_b2 = (const float*)d_in[base + 13];
    const float* ro_w3 = (const float*)d_in[base + 14];
    const float* ro_b3 = (const float*)d_in[base + 15];
    float* out = (float*)d_out;

    cudaFuncSetAttribute(k_edge_mma, cudaFuncAttributeMaxDynamicSharedMemorySize, SM_TOT);
    cudaFuncSetAttribute(k_lstm_mma, cudaFuncAttributeMaxDynamicSharedMemorySize, L_TOT);

    k_prep<<<(PREP_TOTAL + 255) / 256, 256>>>(mp_w1, mp_w2, mp_w3, w_ih, w_hh,
                                              b_ih, b_hh, ro_w1, ro_w2);
    k_prep_pads<<<40, 256>>>();
    k_eaw<<<EEDGE * 16 / 256, 256>>>(ea, mp_b1);
    k_init<<<(SSEG * 256 + 255) / 256, 256>>>();

    for (int t = 0; t < NSTEPS; t++) {
        k_edge_mma<<<EEDGE / 128, 512, SM_TOT>>>(row, col, mp_b2, mp_b3);
        k_lstm_mma<<<(SSEG + 63) / 64, 512, L_TOT>>>();
    }

    k_readout<<<(NNODES + 31) / 32, 128>>>(ro_b1, ro_b2, ro_w3, ro_b3, out);
}